// round 4
// baseline (speedup 1.0000x reference)
#include <cuda_runtime.h>
#include <math.h>

// Problem dims
#define TT   512
#define BB   64
#define HH   300
#define KKT  9
#define G4   1200           // 4*H
#define NCOL 32768          // T*B columns (t*64+b)
#define HB   (HH*BB)        // 19200
#define NSL  74             // slices per direction (1 CTA each); grid = 148

typedef unsigned long long ull;

// ---------------- scratch (device globals; no runtime allocation) ----------------
__device__ float g_xT[(size_t)HH * NCOL];
__device__ float g_pre[(size_t)2 * G4 * NCOL];
__device__ float g_h[(size_t)2 * (TT + 1) * HB];   // [dir][t+1][k][b]
__device__ float g_emis[(size_t)TT * BB * KKT];
__device__ int   g_hist[(size_t)(TT - 1) * BB * KKT];
__device__ float g_bias[2 * G4];
__device__ float g_lossb[BB];
__device__ unsigned int g_bar2[64];                // [0]=fwd ctr, [32]=bwd ctr

// ---------------- f32x2 helpers ----------------
__device__ __forceinline__ ull dup2(float v) {
    ull r; asm("mov.b64 %0, {%1, %1};" : "=l"(r) : "f"(v)); return r;
}
__device__ __forceinline__ ull pack2(float a, float b) {
    ull r; asm("mov.b64 %0, {%1, %2};" : "=l"(r) : "f"(a), "f"(b)); return r;
}
__device__ __forceinline__ ull fma2(ull a, ull b, ull c) {
    ull d; asm("fma.rn.f32x2 %0, %1, %2, %3;" : "=l"(d) : "l"(a), "l"(b), "l"(c)); return d;
}
__device__ __forceinline__ float2 u2f(ull v) {
    float2 r; asm("mov.b64 {%0, %1}, %2;" : "=f"(r.x), "=f"(r.y) : "l"(v)); return r;
}
__device__ __forceinline__ float sig_(float x) { return 1.0f / (1.0f + expf(-x)); }

// ---------------- K0: prep — fused bias, h0 transpose, barrier reset ----------------
__global__ void prep_kernel(const float* __restrict__ b_ih_f, const float* __restrict__ b_hh_f,
                            const float* __restrict__ b_ih_b, const float* __restrict__ b_hh_b,
                            const float* __restrict__ h0)
{
    int idx = blockIdx.x * blockDim.x + threadIdx.x;
    if (idx < 64) g_bar2[idx] = 0u;
    if (idx < 2 * G4) {
        g_bias[idx] = (idx < G4) ? (b_ih_f[idx] + b_hh_f[idx])
                                 : (b_ih_b[idx - G4] + b_hh_b[idx - G4]);
    }
    if (idx < 2 * HB) {
        int dir = idx / HB;
        int rem = idx - dir * HB;
        int k = rem >> 6;
        int b = rem & 63;
        g_h[(size_t)dir * (TT + 1) * HB + (size_t)k * BB + b] = h0[(size_t)(dir * BB + b) * HH + k];
    }
}

// ---------------- K1: embedding gather into transposed layout [d][t*64+b] ----------------
__global__ void gather_kernel(const int* __restrict__ tokens, const float* __restrict__ emb)
{
    int t = blockIdx.x;
    __shared__ int tok[BB];
    if (threadIdx.x < BB) tok[threadIdx.x] = tokens[threadIdx.x * TT + t];
    __syncthreads();
    for (int idx = threadIdx.x; idx < HH * BB; idx += blockDim.x) {
        int d = idx >> 6;
        int b = idx & 63;
        g_xT[(size_t)d * NCOL + (size_t)t * BB + b] = emb[(size_t)tok[b] * HH + d];
    }
}

// ---------------- K2: input projection GEMM (f32x2) ----------------
__global__ void __launch_bounds__(256) gemm_pre_kernel(const float* __restrict__ w_ih_f,
                                                       const float* __restrict__ w_ih_b)
{
    const int M = 2 * G4;
    const int Kd = HH;
    __shared__ __align__(16) ull   As2[8][128];
    __shared__ __align__(16) float Bs[8][128];

    int m0 = blockIdx.y * 128;
    int n0 = blockIdx.x * 128;
    int tid = threadIdx.x;
    int ty = tid >> 4;
    int tx = tid & 15;

    ull acc[8][4];
#pragma unroll
    for (int i = 0; i < 8; i++)
#pragma unroll
        for (int j = 0; j < 4; j++) acc[i][j] = 0ull;

    int lk  = tid & 7;    int lm  = tid >> 3;
    int ln  = tid & 127;  int lkb = tid >> 7;

    for (int k0 = 0; k0 < Kd; k0 += 8) {
#pragma unroll
        for (int p = 0; p < 4; p++) {
            int m = m0 + lm + p * 32;
            int kc = k0 + lk;
            float v = 0.f;
            if (m < M && kc < Kd)
                v = (m < G4) ? w_ih_f[(size_t)m * HH + kc]
                             : w_ih_b[(size_t)(m - G4) * HH + kc];
            As2[lk][lm + p * 32] = dup2(v);
        }
#pragma unroll
        for (int p = 0; p < 4; p++) {
            int kc = k0 + lkb + p * 2;
            Bs[lkb + p * 2][ln] = (kc < Kd) ? g_xT[(size_t)kc * NCOL + n0 + ln] : 0.f;
        }
        __syncthreads();
#pragma unroll
        for (int kk = 0; kk < 8; kk++) {
            ull av[8], bv[4];
#pragma unroll
            for (int i = 0; i < 8; i++) av[i] = As2[kk][ty * 8 + i];
            const ull* bsp = (const ull*)&Bs[kk][0];
#pragma unroll
            for (int j = 0; j < 4; j++) bv[j] = bsp[tx * 4 + j];
#pragma unroll
            for (int i = 0; i < 8; i++)
#pragma unroll
                for (int j = 0; j < 4; j++) acc[i][j] = fma2(av[i], bv[j], acc[i][j]);
        }
        __syncthreads();
    }

#pragma unroll
    for (int i = 0; i < 8; i++) {
        int m = m0 + ty * 8 + i;
        if (m >= M) continue;
        float bvs = g_bias[m];
        float* cp = &g_pre[(size_t)m * NCOL + n0 + tx * 8];
#pragma unroll
        for (int j = 0; j < 4; j++) {
            float2 v = u2f(acc[i][j]);
            *(float2*)(cp + j * 2) = make_float2(v.x + bvs, v.y + bvs);
        }
    }
}

// ---------------- K3: persistent LSTM recurrence v3 ----------------
// 148 CTAs x 128 threads. Thread = (ks 0..7) x (bq 0..15); computes ALL this
// CTA's columns (4 or 5) x 4 gates over 38 k x 4 batch. W (duplicated f32x2)
// in smem; h read once per CTA per step via LDG.128 (__ldcg).
template<int NCC>
__device__ __forceinline__ void dot_body(const float4* __restrict__ hp, const ull* __restrict__ Wp,
                                         float* __restrict__ part, int ks, int bq)
{
    ull acc[NCC][4][2];
#pragma unroll
    for (int c = 0; c < NCC; c++)
#pragma unroll
        for (int g = 0; g < 4; g++) { acc[c][g][0] = 0ull; acc[c][g][1] = 0ull; }

#pragma unroll 2
    for (int kk = 0; kk < 38; kk++) {
        float4 hv = __ldcg(hp + (size_t)kk * 16);
        ull h0 = pack2(hv.x, hv.y);
        ull h1 = pack2(hv.z, hv.w);
        const ull* w = Wp + kk * 20;
#pragma unroll
        for (int c = 0; c < NCC; c++) {
            ulonglong2 wa = *(const ulonglong2*)(w + c * 4);
            ulonglong2 wb = *(const ulonglong2*)(w + c * 4 + 2);
            acc[c][0][0] = fma2(wa.x, h0, acc[c][0][0]);
            acc[c][0][1] = fma2(wa.x, h1, acc[c][0][1]);
            acc[c][1][0] = fma2(wa.y, h0, acc[c][1][0]);
            acc[c][1][1] = fma2(wa.y, h1, acc[c][1][1]);
            acc[c][2][0] = fma2(wb.x, h0, acc[c][2][0]);
            acc[c][2][1] = fma2(wb.x, h1, acc[c][2][1]);
            acc[c][3][0] = fma2(wb.y, h0, acc[c][3][0]);
            acc[c][3][1] = fma2(wb.y, h1, acc[c][3][1]);
        }
    }
#pragma unroll
    for (int c = 0; c < NCC; c++)
#pragma unroll
        for (int g = 0; g < 4; g++) {
            float2 lo = u2f(acc[c][g][0]);
            float2 hi = u2f(acc[c][g][1]);
            *(float4*)&part[(size_t)((ks * 5 + c) * 4 + g) * 64 + bq * 4] =
                make_float4(lo.x, lo.y, hi.x, hi.y);
        }
}

__global__ void __launch_bounds__(128, 1) lstm_rec_kernel(const float* __restrict__ whh_f,
                                                          const float* __restrict__ whh_b,
                                                          const float* __restrict__ c0)
{
    extern __shared__ __align__(16) ull sm[];
    ull*   Wd   = sm;                   // [8ks][38kk][5c][4g] = 6080 ull (48.6KB)
    float* part = (float*)(sm + 6080);  // [8ks][5c][4g][64b]  = 10240 f (40KB)

    const int bid = blockIdx.x;
    const int dir = bid & 1;
    const int s   = bid >> 1;
    const int colbase = (s < 70) ? s * 4 : 280 + (s - 70) * 5;
    const int ncc     = (s < 70) ? 4 : 5;

    const int tid = threadIdx.x;
    const int bq  = tid & 15;
    const int ks  = tid >> 4;

    const float* whh = dir ? whh_b : whh_f;

    // Load W_hh slice (coalesced global reads, duplicated pairs to smem)
    for (int lin = tid; lin < 5 * 4 * 304; lin += 128) {
        int c = lin / 1216;             // 4*304
        int rem = lin - c * 1216;
        int g = rem / 304;
        int kg = rem - g * 304;
        int kss = kg / 38, kk = kg - kss * 38;
        float v = 0.f;
        if (c < ncc && kg < 300) v = whh[(size_t)(g * HH + colbase + c) * HH + kg];
        Wd[((size_t)(kss * 38 + kk) * 5 + c) * 4 + g] = dup2(v);
    }

    // finalize role: thread (ch, fb) handles cols {ch, ch+2, (4 if ch==0 && ncc==5)}
    const int fb = tid & 63;
    const int ch = tid >> 6;
    const int nfc = (ch == 0) ? ((ncc == 5) ? 3 : 2) : 2;
    float cst[3];
    for (int j = 0; j < nfc; j++)
        cst[j] = c0[(size_t)(dir * BB + fb) * HH + colbase + ch + 2 * j];

    __syncthreads();

    float*       ghdir  = g_h + (size_t)dir * (TT + 1) * HB;
    const float* predir = g_pre + (size_t)dir * G4 * NCOL;
    const ull*   Wp     = Wd + (size_t)ks * 38 * 20;
    unsigned int* ctr   = &g_bar2[dir * 32];

    unsigned int target = 0;
    for (int t = 0; t < TT; t++) {
        const int tp = dir ? (TT - 1 - t) : t;

        // prefetch pre-activations (independent of h; hides DRAM latency)
        float pre[3][4];
        {
            const float* pb = predir + (size_t)tp * BB + fb;
            for (int j = 0; j < nfc; j++) {
                int jr = colbase + ch + 2 * j;
#pragma unroll
                for (int g = 0; g < 4; g++)
                    pre[j][g] = __ldcg(pb + (size_t)(g * HH + jr) * NCOL);
            }
        }

        const float4* hp = (const float4*)(ghdir + (size_t)t * HB) + (size_t)ks * 38 * 16 + bq;
        if (ncc == 4) dot_body<4>(hp, Wp, part, ks, bq);
        else          dot_body<5>(hp, Wp, part, ks, bq);

        __syncthreads();

        // finalize: sum 8 k-partials + pre, gates, write h(t+1)
        for (int j = 0; j < nfc; j++) {
            int c = ch + 2 * j;
            float gv[4];
#pragma unroll
            for (int g = 0; g < 4; g++) {
                float a = pre[j][g];
#pragma unroll
                for (int kss = 0; kss < 8; kss++)
                    a += part[(size_t)((kss * 5 + c) * 4 + g) * 64 + fb];
                gv[g] = a;
            }
            float ig = sig_(gv[0]), fg = sig_(gv[1]), gt = tanhf(gv[2]), og = sig_(gv[3]);
            float cc = fg * cst[j] + ig * gt;
            cst[j] = cc;
            ghdir[(size_t)(t + 1) * HB + (size_t)(colbase + c) * BB + fb] = og * tanhf(cc);
        }

        // ---- per-direction grid barrier: release-arrive + acquire-poll ----
        target += NSL;
        __syncthreads();                       // all h stores + part reads done
        if (tid == 0) {
            asm volatile("red.release.gpu.global.add.u32 [%0], 1;" :: "l"(ctr) : "memory");
            unsigned int v;
            do {
                asm volatile("ld.acquire.gpu.global.u32 %0, [%1];" : "=r"(v) : "l"(ctr) : "memory");
            } while (v < target);
        }
        __syncthreads();
    }
}

// ---------------- K4: output projection -> emissions [t][b][k] ----------------
__global__ void proj_kernel(const float* __restrict__ w_out, const float* __restrict__ b_out)
{
    int t = blockIdx.x;
    int tid = threadIdx.x;                     // 576 = 9*64
    int b = tid & 63;
    int k = tid >> 6;
    const float* hf = g_h + (size_t)(t + 1) * HB + b;
    const float* hb = g_h + (size_t)(TT + 1) * HB + (size_t)(TT - t) * HB + b;
    const float* w0 = w_out + (size_t)k * (2 * HH);
    float s = b_out[k];
#pragma unroll 4
    for (int j = 0; j < HH; j++) s = fmaf(hf[(size_t)j * BB], w0[j], s);
#pragma unroll 4
    for (int j = 0; j < HH; j++) s = fmaf(hb[(size_t)j * BB], w0[HH + j], s);
    g_emis[(size_t)t * (BB * KKT) + b * KKT + k] = s;
}

// ---------------- K5: Viterbi decode ----------------
__global__ void viterbi_kernel(const float* __restrict__ start_t, const float* __restrict__ end_t,
                               const float* __restrict__ trans, float* __restrict__ out)
{
    int b = blockIdx.x;
    int k = threadIdx.x;
    __shared__ float sc[KKT], ns[KKT], tr[KKT * KKT];
    for (int i = k; i < KKT * KKT; i += 32) tr[i] = trans[i];
    if (k < KKT) sc[k] = start_t[k] + g_emis[(size_t)b * KKT + k];
    __syncwarp();
    for (int t = 1; t < TT; t++) {
        if (k < KKT) {
            float best = -1e30f; int arg = 0;
#pragma unroll
            for (int kp = 0; kp < KKT; kp++) {
                float v = sc[kp] + tr[kp * KKT + k];
                if (v > best) { best = v; arg = kp; }
            }
            ns[k] = best + g_emis[((size_t)t * BB + b) * KKT + k];
            g_hist[((size_t)(t - 1) * BB + b) * KKT + k] = arg;
        }
        __syncwarp();
        if (k < KKT) sc[k] = ns[k];
        __syncwarp();
    }
    if (k == 0) {
        float best = -1e30f; int last = 0;
#pragma unroll
        for (int kk = 0; kk < KKT; kk++) {
            float v = sc[kk] + end_t[kk];
            if (v > best) { best = v; last = kk; }
        }
        out[(size_t)b * TT + (TT - 1)] = (float)last;
        int tag = last;
        for (int t = TT - 2; t >= 0; t--) {
            tag = g_hist[((size_t)t * BB + b) * KKT + tag];
            out[(size_t)b * TT + t] = (float)tag;
        }
    }
}

// ---------------- K6: CRF NLL per batch element ----------------
__global__ void crf_kernel(const int* __restrict__ tags, const float* __restrict__ start_t,
                           const float* __restrict__ end_t, const float* __restrict__ trans)
{
    int b = blockIdx.x;
    int k = threadIdx.x;
    __shared__ float al[KKT], na[KKT], tr[KKT * KKT];
    for (int i = k; i < KKT * KKT; i += 32) tr[i] = trans[i];
    if (k < KKT) al[k] = start_t[k] + g_emis[(size_t)b * KKT + k];
    __syncwarp();
    for (int t = 1; t < TT; t++) {
        if (k < KKT) {
            float mx = -1e30f;
#pragma unroll
            for (int kp = 0; kp < KKT; kp++) mx = fmaxf(mx, al[kp] + tr[kp * KKT + k]);
            float s = 0.f;
#pragma unroll
            for (int kp = 0; kp < KKT; kp++) s += expf(al[kp] + tr[kp * KKT + k] - mx);
            na[k] = mx + logf(s) + g_emis[((size_t)t * BB + b) * KKT + k];
        }
        __syncwarp();
        if (k < KKT) al[k] = na[k];
        __syncwarp();
    }
    if (k == 0) {
        float mx = -1e30f;
#pragma unroll
        for (int kk = 0; kk < KKT; kk++) mx = fmaxf(mx, al[kk] + end_t[kk]);
        float s = 0.f;
#pragma unroll
        for (int kk = 0; kk < KKT; kk++) s += expf(al[kk] + end_t[kk] - mx);
        float den = mx + logf(s);
        int prev = tags[(size_t)b * TT + 0];
        float num = start_t[prev] + g_emis[(size_t)b * KKT + prev];
        for (int t = 1; t < TT; t++) {
            int tt = tags[(size_t)b * TT + t];
            num += tr[prev * KKT + tt] + g_emis[((size_t)t * BB + b) * KKT + tt];
            prev = tt;
        }
        num += end_t[prev];
        g_lossb[b] = den - num;
    }
}

// ---------------- K7: deterministic loss reduction ----------------
__global__ void finalize_kernel(float* __restrict__ out)
{
    if (blockIdx.x == 0 && threadIdx.x == 0) {
        float s = 0.f;
        for (int b = 0; b < BB; b++) s += g_lossb[b];
        out[(size_t)BB * TT] = s;
    }
}

// ---------------- launch ----------------
extern "C" void kernel_launch(void* const* d_in, const int* in_sizes, int n_in,
                              void* d_out, int out_size)
{
    const int*   tokens  = (const int*)  d_in[0];
    const int*   tags    = (const int*)  d_in[1];
    // d_in[2] = mask (all ones by construction; unused)
    const float* emb     = (const float*)d_in[3];
    const float* w_ih_f  = (const float*)d_in[4];
    const float* w_hh_f  = (const float*)d_in[5];
    const float* b_ih_f  = (const float*)d_in[6];
    const float* b_hh_f  = (const float*)d_in[7];
    const float* w_ih_b  = (const float*)d_in[8];
    const float* w_hh_b  = (const float*)d_in[9];
    const float* b_ih_b  = (const float*)d_in[10];
    const float* b_hh_b  = (const float*)d_in[11];
    const float* h0      = (const float*)d_in[12];
    const float* c0      = (const float*)d_in[13];
    const float* w_out   = (const float*)d_in[14];
    const float* b_out   = (const float*)d_in[15];
    const float* start_t = (const float*)d_in[16];
    const float* end_t   = (const float*)d_in[17];
    const float* trans   = (const float*)d_in[18];
    float* out = (float*)d_out;

    static int smem_set = 0;
    if (!smem_set) {
        cudaFuncSetAttribute(lstm_rec_kernel, cudaFuncAttributeMaxDynamicSharedMemorySize, 98304);
        smem_set = 1;
    }
    const int rec_smem = 6080 * 8 + 10240 * 4;   // 89600 bytes

    prep_kernel<<<150, 256>>>(b_ih_f, b_hh_f, b_ih_b, b_hh_b, h0);
    gather_kernel<<<TT, 256>>>(tokens, emb);
    gemm_pre_kernel<<<dim3(NCOL / 128, 19), 256>>>(w_ih_f, w_ih_b);
    lstm_rec_kernel<<<2 * NSL, 128, rec_smem>>>(w_hh_f, w_hh_b, c0);
    proj_kernel<<<TT, 576>>>(w_out, b_out);
    viterbi_kernel<<<BB, 32>>>(start_t, end_t, trans, out);
    crf_kernel<<<BB, 32>>>(tags, start_t, end_t, trans);
    finalize_kernel<<<1, 1>>>(out);
}

// round 5
// speedup vs baseline: 1.0037x; 1.0037x over previous
#include <cuda_runtime.h>
#include <math.h>

// Problem dims
#define TT   512
#define BB   64
#define HH   300
#define KKT  9
#define G4   1200           // 4*H
#define NCOL 32768          // T*B columns (t*64+b)
#define HB   (HH*BB)        // 19200
#define NSL  74             // slices per direction (1 CTA each); grid = 148

typedef unsigned long long ull;

// ---------------- scratch (device globals; no runtime allocation) ----------------
__device__ float g_xT[(size_t)HH * NCOL];
__device__ float g_pre[(size_t)2 * G4 * NCOL];
__device__ float g_h[(size_t)2 * (TT + 1) * HB];   // [dir][t+1][k][b]
__device__ float g_emis[(size_t)TT * BB * KKT];
__device__ int   g_hist[(size_t)(TT - 1) * BB * KKT];
__device__ float g_bias[2 * G4];
__device__ float g_lossb[BB];
__device__ unsigned int g_bar2[64];                // [0]=fwd ctr, [32]=bwd ctr

// ---------------- f32x2 helpers ----------------
__device__ __forceinline__ ull dup2(float v) {
    ull r; asm("mov.b64 %0, {%1, %1};" : "=l"(r) : "f"(v)); return r;
}
__device__ __forceinline__ ull pack2(float a, float b) {
    ull r; asm("mov.b64 %0, {%1, %2};" : "=l"(r) : "f"(a), "f"(b)); return r;
}
__device__ __forceinline__ ull fma2(ull a, ull b, ull c) {
    ull d; asm("fma.rn.f32x2 %0, %1, %2, %3;" : "=l"(d) : "l"(a), "l"(b), "l"(c)); return d;
}
__device__ __forceinline__ float2 u2f(ull v) {
    float2 r; asm("mov.b64 {%0, %1}, %2;" : "=f"(r.x), "=f"(r.y) : "l"(v)); return r;
}
__device__ __forceinline__ float sig_(float x) { return 1.0f / (1.0f + expf(-x)); }

// ---------------- K0: prep — fused bias, h0 transpose, barrier reset ----------------
__global__ void prep_kernel(const float* __restrict__ b_ih_f, const float* __restrict__ b_hh_f,
                            const float* __restrict__ b_ih_b, const float* __restrict__ b_hh_b,
                            const float* __restrict__ h0)
{
    int idx = blockIdx.x * blockDim.x + threadIdx.x;
    if (idx < 64) g_bar2[idx] = 0u;
    if (idx < 2 * G4) {
        g_bias[idx] = (idx < G4) ? (b_ih_f[idx] + b_hh_f[idx])
                                 : (b_ih_b[idx - G4] + b_hh_b[idx - G4]);
    }
    if (idx < 2 * HB) {
        int dir = idx / HB;
        int rem = idx - dir * HB;
        int k = rem >> 6;
        int b = rem & 63;
        g_h[(size_t)dir * (TT + 1) * HB + (size_t)k * BB + b] = h0[(size_t)(dir * BB + b) * HH + k];
    }
}

// ---------------- K1: embedding gather into transposed layout [d][t*64+b] ----------------
__global__ void gather_kernel(const int* __restrict__ tokens, const float* __restrict__ emb)
{
    int t = blockIdx.x;
    __shared__ int tok[BB];
    if (threadIdx.x < BB) tok[threadIdx.x] = tokens[threadIdx.x * TT + t];
    __syncthreads();
    for (int idx = threadIdx.x; idx < HH * BB; idx += blockDim.x) {
        int d = idx >> 6;
        int b = idx & 63;
        g_xT[(size_t)d * NCOL + (size_t)t * BB + b] = emb[(size_t)tok[b] * HH + d];
    }
}

// ---------------- K2: input projection GEMM (f32x2) ----------------
__global__ void __launch_bounds__(256) gemm_pre_kernel(const float* __restrict__ w_ih_f,
                                                       const float* __restrict__ w_ih_b)
{
    const int M = 2 * G4;
    const int Kd = HH;
    __shared__ __align__(16) ull   As2[8][128];
    __shared__ __align__(16) float Bs[8][128];

    int m0 = blockIdx.y * 128;
    int n0 = blockIdx.x * 128;
    int tid = threadIdx.x;
    int ty = tid >> 4;
    int tx = tid & 15;

    ull acc[8][4];
#pragma unroll
    for (int i = 0; i < 8; i++)
#pragma unroll
        for (int j = 0; j < 4; j++) acc[i][j] = 0ull;

    int lk  = tid & 7;    int lm  = tid >> 3;
    int ln  = tid & 127;  int lkb = tid >> 7;

    for (int k0 = 0; k0 < Kd; k0 += 8) {
#pragma unroll
        for (int p = 0; p < 4; p++) {
            int m = m0 + lm + p * 32;
            int kc = k0 + lk;
            float v = 0.f;
            if (m < M && kc < Kd)
                v = (m < G4) ? w_ih_f[(size_t)m * HH + kc]
                             : w_ih_b[(size_t)(m - G4) * HH + kc];
            As2[lk][lm + p * 32] = dup2(v);
        }
#pragma unroll
        for (int p = 0; p < 4; p++) {
            int kc = k0 + lkb + p * 2;
            Bs[lkb + p * 2][ln] = (kc < Kd) ? g_xT[(size_t)kc * NCOL + n0 + ln] : 0.f;
        }
        __syncthreads();
#pragma unroll
        for (int kk = 0; kk < 8; kk++) {
            ull av[8], bv[4];
#pragma unroll
            for (int i = 0; i < 8; i++) av[i] = As2[kk][ty * 8 + i];
            const ull* bsp = (const ull*)&Bs[kk][0];
#pragma unroll
            for (int j = 0; j < 4; j++) bv[j] = bsp[tx * 4 + j];
#pragma unroll
            for (int i = 0; i < 8; i++)
#pragma unroll
                for (int j = 0; j < 4; j++) acc[i][j] = fma2(av[i], bv[j], acc[i][j]);
        }
        __syncthreads();
    }

#pragma unroll
    for (int i = 0; i < 8; i++) {
        int m = m0 + ty * 8 + i;
        if (m >= M) continue;
        float bvs = g_bias[m];
        float* cp = &g_pre[(size_t)m * NCOL + n0 + tx * 8];
#pragma unroll
        for (int j = 0; j < 4; j++) {
            float2 v = u2f(acc[i][j]);
            *(float2*)(cp + j * 2) = make_float2(v.x + bvs, v.y + bvs);
        }
    }
}

// ---------------- K3: persistent LSTM recurrence v3 ----------------
// 148 CTAs x 128 threads. Thread = (ks 0..7) x (bq 0..15); computes ALL this
// CTA's columns (4 or 5) x 4 gates over 38 k x 4 batch. W (duplicated f32x2)
// in smem; h read once per CTA per step via LDG.128 (__ldcg).
template<int NCC>
__device__ __forceinline__ void dot_body(const float4* __restrict__ hp, const ull* __restrict__ Wp,
                                         float* __restrict__ part, int ks, int bq)
{
    ull acc[NCC][4][2];
#pragma unroll
    for (int c = 0; c < NCC; c++)
#pragma unroll
        for (int g = 0; g < 4; g++) { acc[c][g][0] = 0ull; acc[c][g][1] = 0ull; }

#pragma unroll 2
    for (int kk = 0; kk < 38; kk++) {
        float4 hv = __ldcg(hp + (size_t)kk * 16);
        ull h0 = pack2(hv.x, hv.y);
        ull h1 = pack2(hv.z, hv.w);
        const ull* w = Wp + kk * 20;
#pragma unroll
        for (int c = 0; c < NCC; c++) {
            ulonglong2 wa = *(const ulonglong2*)(w + c * 4);
            ulonglong2 wb = *(const ulonglong2*)(w + c * 4 + 2);
            acc[c][0][0] = fma2(wa.x, h0, acc[c][0][0]);
            acc[c][0][1] = fma2(wa.x, h1, acc[c][0][1]);
            acc[c][1][0] = fma2(wa.y, h0, acc[c][1][0]);
            acc[c][1][1] = fma2(wa.y, h1, acc[c][1][1]);
            acc[c][2][0] = fma2(wb.x, h0, acc[c][2][0]);
            acc[c][2][1] = fma2(wb.x, h1, acc[c][2][1]);
            acc[c][3][0] = fma2(wb.y, h0, acc[c][3][0]);
            acc[c][3][1] = fma2(wb.y, h1, acc[c][3][1]);
        }
    }
#pragma unroll
    for (int c = 0; c < NCC; c++)
#pragma unroll
        for (int g = 0; g < 4; g++) {
            float2 lo = u2f(acc[c][g][0]);
            float2 hi = u2f(acc[c][g][1]);
            *(float4*)&part[(size_t)((ks * 5 + c) * 4 + g) * 64 + bq * 4] =
                make_float4(lo.x, lo.y, hi.x, hi.y);
        }
}

__global__ void __launch_bounds__(128, 1) lstm_rec_kernel(const float* __restrict__ whh_f,
                                                          const float* __restrict__ whh_b,
                                                          const float* __restrict__ c0)
{
    extern __shared__ __align__(16) ull sm[];
    ull*   Wd   = sm;                   // [8ks][38kk][5c][4g] = 6080 ull (48.6KB)
    float* part = (float*)(sm + 6080);  // [8ks][5c][4g][64b]  = 10240 f (40KB)

    const int bid = blockIdx.x;
    const int dir = bid & 1;
    const int s   = bid >> 1;
    const int colbase = (s < 70) ? s * 4 : 280 + (s - 70) * 5;
    const int ncc     = (s < 70) ? 4 : 5;

    const int tid = threadIdx.x;
    const int bq  = tid & 15;
    const int ks  = tid >> 4;

    const float* whh = dir ? whh_b : whh_f;

    // Load W_hh slice (coalesced global reads, duplicated pairs to smem)
    for (int lin = tid; lin < 5 * 4 * 304; lin += 128) {
        int c = lin / 1216;             // 4*304
        int rem = lin - c * 1216;
        int g = rem / 304;
        int kg = rem - g * 304;
        int kss = kg / 38, kk = kg - kss * 38;
        float v = 0.f;
        if (c < ncc && kg < 300) v = whh[(size_t)(g * HH + colbase + c) * HH + kg];
        Wd[((size_t)(kss * 38 + kk) * 5 + c) * 4 + g] = dup2(v);
    }

    // finalize role: thread (ch, fb) handles cols {ch, ch+2, (4 if ch==0 && ncc==5)}
    const int fb = tid & 63;
    const int ch = tid >> 6;
    const int nfc = (ch == 0) ? ((ncc == 5) ? 3 : 2) : 2;
    float cst[3];
    for (int j = 0; j < nfc; j++)
        cst[j] = c0[(size_t)(dir * BB + fb) * HH + colbase + ch + 2 * j];

    __syncthreads();

    float*       ghdir  = g_h + (size_t)dir * (TT + 1) * HB;
    const float* predir = g_pre + (size_t)dir * G4 * NCOL;
    const ull*   Wp     = Wd + (size_t)ks * 38 * 20;
    unsigned int* ctr   = &g_bar2[dir * 32];

    unsigned int target = 0;
    for (int t = 0; t < TT; t++) {
        const int tp = dir ? (TT - 1 - t) : t;

        // prefetch pre-activations (independent of h; hides DRAM latency)
        float pre[3][4];
        {
            const float* pb = predir + (size_t)tp * BB + fb;
            for (int j = 0; j < nfc; j++) {
                int jr = colbase + ch + 2 * j;
#pragma unroll
                for (int g = 0; g < 4; g++)
                    pre[j][g] = __ldcg(pb + (size_t)(g * HH + jr) * NCOL);
            }
        }

        const float4* hp = (const float4*)(ghdir + (size_t)t * HB) + (size_t)ks * 38 * 16 + bq;
        if (ncc == 4) dot_body<4>(hp, Wp, part, ks, bq);
        else          dot_body<5>(hp, Wp, part, ks, bq);

        __syncthreads();

        // finalize: sum 8 k-partials + pre, gates, write h(t+1)
        for (int j = 0; j < nfc; j++) {
            int c = ch + 2 * j;
            float gv[4];
#pragma unroll
            for (int g = 0; g < 4; g++) {
                float a = pre[j][g];
#pragma unroll
                for (int kss = 0; kss < 8; kss++)
                    a += part[(size_t)((kss * 5 + c) * 4 + g) * 64 + fb];
                gv[g] = a;
            }
            float ig = sig_(gv[0]), fg = sig_(gv[1]), gt = tanhf(gv[2]), og = sig_(gv[3]);
            float cc = fg * cst[j] + ig * gt;
            cst[j] = cc;
            ghdir[(size_t)(t + 1) * HB + (size_t)(colbase + c) * BB + fb] = og * tanhf(cc);
        }

        // ---- per-direction grid barrier: release-arrive + acquire-poll ----
        target += NSL;
        __syncthreads();                       // all h stores + part reads done
        if (tid == 0) {
            asm volatile("red.release.gpu.global.add.u32 [%0], 1;" :: "l"(ctr) : "memory");
            unsigned int v;
            do {
                asm volatile("ld.acquire.gpu.global.u32 %0, [%1];" : "=r"(v) : "l"(ctr) : "memory");
            } while (v < target);
        }
        __syncthreads();
    }
}

// ---------------- K4: output projection -> emissions [t][b][k] ----------------
__global__ void proj_kernel(const float* __restrict__ w_out, const float* __restrict__ b_out)
{
    int t = blockIdx.x;
    int tid = threadIdx.x;                     // 576 = 9*64
    int b = tid & 63;
    int k = tid >> 6;
    const float* hf = g_h + (size_t)(t + 1) * HB + b;
    const float* hb = g_h + (size_t)(TT + 1) * HB + (size_t)(TT - t) * HB + b;
    const float* w0 = w_out + (size_t)k * (2 * HH);
    float s = b_out[k];
#pragma unroll 4
    for (int j = 0; j < HH; j++) s = fmaf(hf[(size_t)j * BB], w0[j], s);
#pragma unroll 4
    for (int j = 0; j < HH; j++) s = fmaf(hb[(size_t)j * BB], w0[HH + j], s);
    g_emis[(size_t)t * (BB * KKT) + b * KKT + k] = s;
}

// ---------------- K5: Viterbi decode ----------------
__global__ void viterbi_kernel(const float* __restrict__ start_t, const float* __restrict__ end_t,
                               const float* __restrict__ trans, float* __restrict__ out)
{
    int b = blockIdx.x;
    int k = threadIdx.x;
    __shared__ float sc[KKT], ns[KKT], tr[KKT * KKT];
    for (int i = k; i < KKT * KKT; i += 32) tr[i] = trans[i];
    if (k < KKT) sc[k] = start_t[k] + g_emis[(size_t)b * KKT + k];
    __syncwarp();
    for (int t = 1; t < TT; t++) {
        if (k < KKT) {
            float best = -1e30f; int arg = 0;
#pragma unroll
            for (int kp = 0; kp < KKT; kp++) {
                float v = sc[kp] + tr[kp * KKT + k];
                if (v > best) { best = v; arg = kp; }
            }
            ns[k] = best + g_emis[((size_t)t * BB + b) * KKT + k];
            g_hist[((size_t)(t - 1) * BB + b) * KKT + k] = arg;
        }
        __syncwarp();
        if (k < KKT) sc[k] = ns[k];
        __syncwarp();
    }
    if (k == 0) {
        float best = -1e30f; int last = 0;
#pragma unroll
        for (int kk = 0; kk < KKT; kk++) {
            float v = sc[kk] + end_t[kk];
            if (v > best) { best = v; last = kk; }
        }
        out[(size_t)b * TT + (TT - 1)] = (float)last;
        int tag = last;
        for (int t = TT - 2; t >= 0; t--) {
            tag = g_hist[((size_t)t * BB + b) * KKT + tag];
            out[(size_t)b * TT + t] = (float)tag;
        }
    }
}

// ---------------- K6: CRF NLL per batch element ----------------
__global__ void crf_kernel(const int* __restrict__ tags, const float* __restrict__ start_t,
                           const float* __restrict__ end_t, const float* __restrict__ trans)
{
    int b = blockIdx.x;
    int k = threadIdx.x;
    __shared__ float al[KKT], na[KKT], tr[KKT * KKT];
    for (int i = k; i < KKT * KKT; i += 32) tr[i] = trans[i];
    if (k < KKT) al[k] = start_t[k] + g_emis[(size_t)b * KKT + k];
    __syncwarp();
    for (int t = 1; t < TT; t++) {
        if (k < KKT) {
            float mx = -1e30f;
#pragma unroll
            for (int kp = 0; kp < KKT; kp++) mx = fmaxf(mx, al[kp] + tr[kp * KKT + k]);
            float s = 0.f;
#pragma unroll
            for (int kp = 0; kp < KKT; kp++) s += expf(al[kp] + tr[kp * KKT + k] - mx);
            na[k] = mx + logf(s) + g_emis[((size_t)t * BB + b) * KKT + k];
        }
        __syncwarp();
        if (k < KKT) al[k] = na[k];
        __syncwarp();
    }
    if (k == 0) {
        float mx = -1e30f;
#pragma unroll
        for (int kk = 0; kk < KKT; kk++) mx = fmaxf(mx, al[kk] + end_t[kk]);
        float s = 0.f;
#pragma unroll
        for (int kk = 0; kk < KKT; kk++) s += expf(al[kk] + end_t[kk] - mx);
        float den = mx + logf(s);
        int prev = tags[(size_t)b * TT + 0];
        float num = start_t[prev] + g_emis[(size_t)b * KKT + prev];
        for (int t = 1; t < TT; t++) {
            int tt = tags[(size_t)b * TT + t];
            num += tr[prev * KKT + tt] + g_emis[((size_t)t * BB + b) * KKT + tt];
            prev = tt;
        }
        num += end_t[prev];
        g_lossb[b] = den - num;
    }
}

// ---------------- K7: deterministic loss reduction ----------------
__global__ void finalize_kernel(float* __restrict__ out)
{
    if (blockIdx.x == 0 && threadIdx.x == 0) {
        float s = 0.f;
        for (int b = 0; b < BB; b++) s += g_lossb[b];
        out[(size_t)BB * TT] = s;
    }
}

// ---------------- launch ----------------
extern "C" void kernel_launch(void* const* d_in, const int* in_sizes, int n_in,
                              void* d_out, int out_size)
{
    const int*   tokens  = (const int*)  d_in[0];
    const int*   tags    = (const int*)  d_in[1];
    // d_in[2] = mask (all ones by construction; unused)
    const float* emb     = (const float*)d_in[3];
    const float* w_ih_f  = (const float*)d_in[4];
    const float* w_hh_f  = (const float*)d_in[5];
    const float* b_ih_f  = (const float*)d_in[6];
    const float* b_hh_f  = (const float*)d_in[7];
    const float* w_ih_b  = (const float*)d_in[8];
    const float* w_hh_b  = (const float*)d_in[9];
    const float* b_ih_b  = (const float*)d_in[10];
    const float* b_hh_b  = (const float*)d_in[11];
    const float* h0      = (const float*)d_in[12];
    const float* c0      = (const float*)d_in[13];
    const float* w_out   = (const float*)d_in[14];
    const float* b_out   = (const float*)d_in[15];
    const float* start_t = (const float*)d_in[16];
    const float* end_t   = (const float*)d_in[17];
    const float* trans   = (const float*)d_in[18];
    float* out = (float*)d_out;

    static int smem_set = 0;
    if (!smem_set) {
        cudaFuncSetAttribute(lstm_rec_kernel, cudaFuncAttributeMaxDynamicSharedMemorySize, 98304);
        smem_set = 1;
    }
    const int rec_smem = 6080 * 8 + 10240 * 4;   // 89600 bytes

    prep_kernel<<<150, 256>>>(b_ih_f, b_hh_f, b_ih_b, b_hh_b, h0);
    gather_kernel<<<TT, 256>>>(tokens, emb);
    gemm_pre_kernel<<<dim3(NCOL / 128, 19), 256>>>(w_ih_f, w_ih_b);
    lstm_rec_kernel<<<2 * NSL, 128, rec_smem>>>(w_hh_f, w_hh_b, c0);
    proj_kernel<<<TT, 576>>>(w_out, b_out);
    viterbi_kernel<<<BB, 32>>>(start_t, end_t, trans, out);
    crf_kernel<<<BB, 32>>>(tags, start_t, end_t, trans);
    finalize_kernel<<<1, 1>>>(out);
}

// round 6
// speedup vs baseline: 1.2376x; 1.2330x over previous
#include <cuda_runtime.h>
#include <math.h>

// Problem dims
#define TT   512
#define BB   64
#define HH   300
#define KKT  9
#define G4   1200           // 4*H
#define NCOL 32768          // T*B columns (t*64+b)
#define HB   (HH*BB)        // 19200
#define NSL  75             // slices per direction (4 cols each); grid = 150
#define PSTR 68             // padded part row stride (floats)

typedef unsigned long long ull;

// ---------------- scratch (device globals; no runtime allocation) ----------------
__device__ __align__(16) float g_xT[(size_t)HH * NCOL];
__device__ __align__(16) float g_pre[(size_t)2 * G4 * NCOL];
__device__ __align__(16) float g_h[(size_t)2 * (TT + 1) * HB];   // [dir][t+1][k][b]
__device__ float g_emis[(size_t)TT * BB * KKT];
__device__ int   g_hist[(size_t)(TT - 1) * BB * KKT];
__device__ float g_bias[2 * G4];
__device__ float g_lossb[BB];
__device__ unsigned int g_bar2[64];                // [0]=fwd ctr, [32]=bwd ctr

// ---------------- helpers ----------------
__device__ __forceinline__ ull dup2(float v) {
    ull r; asm("mov.b64 %0, {%1, %1};" : "=l"(r) : "f"(v)); return r;
}
__device__ __forceinline__ ull fma2(ull a, ull b, ull c) {
    ull d; asm("fma.rn.f32x2 %0, %1, %2, %3;" : "=l"(d) : "l"(a), "l"(b), "l"(c)); return d;
}
__device__ __forceinline__ float2 u2f(ull v) {
    float2 r; asm("mov.b64 {%0, %1}, %2;" : "=f"(r.x), "=f"(r.y) : "l"(v)); return r;
}
__device__ __forceinline__ float sig_(float x) { return 1.0f / (1.0f + expf(-x)); }
__device__ __forceinline__ unsigned int smem_u32(const void* p) {
    unsigned int a;
    asm("{ .reg .u64 t; cvta.to.shared.u64 t, %1; cvt.u32.u64 %0, t; }" : "=r"(a) : "l"(p));
    return a;
}
__device__ __forceinline__ void cpa16(unsigned int dst, const void* src) {
    asm volatile("cp.async.cg.shared.global [%0], [%1], 16;" :: "r"(dst), "l"(src) : "memory");
}

// ---------------- K0: prep — fused bias, h0 transpose, barrier reset ----------------
__global__ void prep_kernel(const float* __restrict__ b_ih_f, const float* __restrict__ b_hh_f,
                            const float* __restrict__ b_ih_b, const float* __restrict__ b_hh_b,
                            const float* __restrict__ h0)
{
    int idx = blockIdx.x * blockDim.x + threadIdx.x;
    if (idx < 64) g_bar2[idx] = 0u;
    if (idx < 2 * G4) {
        g_bias[idx] = (idx < G4) ? (b_ih_f[idx] + b_hh_f[idx])
                                 : (b_ih_b[idx - G4] + b_hh_b[idx - G4]);
    }
    if (idx < 2 * HB) {
        int dir = idx / HB;
        int rem = idx - dir * HB;
        int k = rem >> 6;
        int b = rem & 63;
        g_h[(size_t)dir * (TT + 1) * HB + (size_t)k * BB + b] = h0[(size_t)(dir * BB + b) * HH + k];
    }
}

// ---------------- K1: embedding gather into transposed layout [d][t*64+b] ----------------
__global__ void gather_kernel(const int* __restrict__ tokens, const float* __restrict__ emb)
{
    int t = blockIdx.x;
    __shared__ int tok[BB];
    if (threadIdx.x < BB) tok[threadIdx.x] = tokens[threadIdx.x * TT + t];
    __syncthreads();
    for (int idx = threadIdx.x; idx < HH * BB; idx += blockDim.x) {
        int d = idx >> 6;
        int b = idx & 63;
        g_xT[(size_t)d * NCOL + (size_t)t * BB + b] = emb[(size_t)tok[b] * HH + d];
    }
}

// ---------------- K2: input projection GEMM (f32x2) ----------------
__global__ void __launch_bounds__(256) gemm_pre_kernel(const float* __restrict__ w_ih_f,
                                                       const float* __restrict__ w_ih_b)
{
    const int M = 2 * G4;
    const int Kd = HH;
    __shared__ __align__(16) ull   As2[8][128];
    __shared__ __align__(16) float Bs[8][128];

    int m0 = blockIdx.y * 128;
    int n0 = blockIdx.x * 128;
    int tid = threadIdx.x;
    int ty = tid >> 4;
    int tx = tid & 15;

    ull acc[8][4];
#pragma unroll
    for (int i = 0; i < 8; i++)
#pragma unroll
        for (int j = 0; j < 4; j++) acc[i][j] = 0ull;

    int lk  = tid & 7;    int lm  = tid >> 3;
    int ln  = tid & 127;  int lkb = tid >> 7;

    for (int k0 = 0; k0 < Kd; k0 += 8) {
#pragma unroll
        for (int p = 0; p < 4; p++) {
            int m = m0 + lm + p * 32;
            int kc = k0 + lk;
            float v = 0.f;
            if (m < M && kc < Kd)
                v = (m < G4) ? w_ih_f[(size_t)m * HH + kc]
                             : w_ih_b[(size_t)(m - G4) * HH + kc];
            As2[lk][lm + p * 32] = dup2(v);
        }
#pragma unroll
        for (int p = 0; p < 4; p++) {
            int kc = k0 + lkb + p * 2;
            Bs[lkb + p * 2][ln] = (kc < Kd) ? g_xT[(size_t)kc * NCOL + n0 + ln] : 0.f;
        }
        __syncthreads();
#pragma unroll
        for (int kk = 0; kk < 8; kk++) {
            ull av[8], bv[4];
#pragma unroll
            for (int i = 0; i < 8; i++) av[i] = As2[kk][ty * 8 + i];
            const ull* bsp = (const ull*)&Bs[kk][0];
#pragma unroll
            for (int j = 0; j < 4; j++) bv[j] = bsp[tx * 4 + j];
#pragma unroll
            for (int i = 0; i < 8; i++)
#pragma unroll
                for (int j = 0; j < 4; j++) acc[i][j] = fma2(av[i], bv[j], acc[i][j]);
        }
        __syncthreads();
    }

#pragma unroll
    for (int i = 0; i < 8; i++) {
        int m = m0 + ty * 8 + i;
        if (m >= M) continue;
        float bvs = g_bias[m];
        float* cp = &g_pre[(size_t)m * NCOL + n0 + tx * 8];
#pragma unroll
        for (int j = 0; j < 4; j++) {
            float2 v = u2f(acc[i][j]);
            *(float2*)(cp + j * 2) = make_float2(v.x + bvs, v.y + bvs);
        }
    }
}

// ---------------- K3: persistent LSTM recurrence v4 ----------------
// grid = 150 (2 dir x 75 slices of 4 cols), 256 threads (8 warps).
// Thread (ks, cgp, bh): W (38 dup'd f32x2 values) lives in REGISTERS for the
// whole launch. Each warp cp.async-stages its own 38 h rows into smem (warp-
// local, no CTA sync), then runs the dot from LDS. acc = 16 f32x2 pairs
// (32 batch). Partials reduced through smem by the finalize role (1 col/thread).
__global__ void __launch_bounds__(256, 1) lstm_rec_kernel(const float* __restrict__ whh_f,
                                                          const float* __restrict__ whh_b,
                                                          const float* __restrict__ c0)
{
    extern __shared__ __align__(16) float sm_f[];
    float* h_sm = sm_f;                       // [304][64] floats  (77824 B)
    float* part = sm_f + 304 * 64;            // [128][PSTR] floats (34816 B)

    const int bid = blockIdx.x;
    const int dir = bid & 1;
    const int s   = bid >> 1;                 // 0..74
    const int colbase = s * 4;

    const int tid  = threadIdx.x;
    const int ks   = tid >> 5;                // 0..7 (38 k each, padded to 304)
    const int lane = tid & 31;
    const int cgp  = lane >> 1;               // 0..15 -> (c,g)
    const int bh   = lane & 1;                // batch half (32 each)
    const int c    = cgp >> 2;
    const int g    = cgp & 3;

    const float* whh = dir ? whh_b : whh_f;

    // zero-pad staged rows 300..303 (read by ks=7, never written by staging)
    h_sm[300 * 64 + tid] = 0.f;

    // W_hh slice -> registers (duplicated pairs), loaded once per launch
    ull Wr[38];
#pragma unroll
    for (int kk = 0; kk < 38; kk++) {
        int k = ks * 38 + kk;
        float v = (k < 300) ? whh[(size_t)(g * HH + colbase + c) * HH + k] : 0.f;
        Wr[kk] = dup2(v);
    }

    // finalize role: 1 column per thread
    const int ffc = tid >> 6;                 // 0..3
    const int ffb = tid & 63;
    float cst = c0[(size_t)(dir * BB + ffb) * HH + colbase + ffc];

    __syncthreads();

    float*       ghdir  = g_h + (size_t)dir * (TT + 1) * HB;
    const float* predir = g_pre + (size_t)dir * G4 * NCOL;
    unsigned int* ctr   = &g_bar2[dir * 32];

    const int nf4 = ((ks < 7) ? 38 : 34) * 16;           // float4s this warp stages
    const unsigned int hdst0 = smem_u32(h_sm + ks * 38 * 64);
    const float* hbase = h_sm + ks * 38 * 64 + bh * 32;
    float* pp = part + (size_t)(ks * 16 + cgp) * PSTR + bh * 32;

    unsigned int target = 0;
    for (int t = 0; t < TT; t++) {
        const int tp = dir ? (TT - 1 - t) : t;

        // prefetch pre-activations for finalize (hidden behind the dot)
        const float* pb = predir + (size_t)tp * BB + ffb;
        float pre0 = __ldcg(pb + (size_t)(0 * HH + colbase + ffc) * NCOL);
        float pre1 = __ldcg(pb + (size_t)(1 * HH + colbase + ffc) * NCOL);
        float pre2 = __ldcg(pb + (size_t)(2 * HH + colbase + ffc) * NCOL);
        float pre3 = __ldcg(pb + (size_t)(3 * HH + colbase + ffc) * NCOL);

        // warp-local h staging (bulk MLP, no CTA-wide sync)
        const float4* hsrc = (const float4*)(ghdir + (size_t)t * HB) + ks * 38 * 16;
        for (int i = lane; i < nf4; i += 32)
            cpa16(hdst0 + i * 16, hsrc + i);
        asm volatile("cp.async.commit_group;" ::: "memory");
        asm volatile("cp.async.wait_group 0;" ::: "memory");
        __syncwarp();

        // dot: 38 k x 32 batch for this thread's (col,gate); W in registers
        ull acc[16];
#pragma unroll
        for (int i = 0; i < 16; i++) acc[i] = 0ull;
#pragma unroll
        for (int kk = 0; kk < 38; kk++) {
            const ulonglong2* hp = (const ulonglong2*)(hbase + kk * 64);
            ull w = Wr[kk];
            ulonglong2 p0 = hp[0], p1 = hp[1], p2 = hp[2], p3 = hp[3];
            acc[0] = fma2(w, p0.x, acc[0]);  acc[1] = fma2(w, p0.y, acc[1]);
            acc[2] = fma2(w, p1.x, acc[2]);  acc[3] = fma2(w, p1.y, acc[3]);
            acc[4] = fma2(w, p2.x, acc[4]);  acc[5] = fma2(w, p2.y, acc[5]);
            acc[6] = fma2(w, p3.x, acc[6]);  acc[7] = fma2(w, p3.y, acc[7]);
            ulonglong2 p4 = hp[4], p5 = hp[5], p6 = hp[6], p7 = hp[7];
            acc[8]  = fma2(w, p4.x, acc[8]);  acc[9]  = fma2(w, p4.y, acc[9]);
            acc[10] = fma2(w, p5.x, acc[10]); acc[11] = fma2(w, p5.y, acc[11]);
            acc[12] = fma2(w, p6.x, acc[12]); acc[13] = fma2(w, p6.y, acc[13]);
            acc[14] = fma2(w, p7.x, acc[14]); acc[15] = fma2(w, p7.y, acc[15]);
        }

        // store partials
#pragma unroll
        for (int j = 0; j < 8; j++) {
            ulonglong2 v; v.x = acc[2 * j]; v.y = acc[2 * j + 1];
            *(ulonglong2*)(pp + j * 4) = v;
        }
        __syncthreads();

        // finalize: sum 8 k-partials + pre, gates, write h(t+1)
        {
            float gv0 = pre0, gv1 = pre1, gv2 = pre2, gv3 = pre3;
#pragma unroll
            for (int kss = 0; kss < 8; kss++) {
                const float* pr = part + (size_t)(kss * 16 + ffc * 4) * PSTR + ffb;
                gv0 += pr[0];
                gv1 += pr[PSTR];
                gv2 += pr[2 * PSTR];
                gv3 += pr[3 * PSTR];
            }
            float ig = sig_(gv0), fg = sig_(gv1), gt = tanhf(gv2), og = sig_(gv3);
            cst = fg * cst + ig * gt;
            ghdir[(size_t)(t + 1) * HB + (size_t)(colbase + ffc) * BB + ffb] = og * tanhf(cst);
        }

        // per-direction grid barrier: release-arrive + acquire-poll
        target += NSL;
        __syncthreads();
        if (tid == 0) {
            asm volatile("red.release.gpu.global.add.u32 [%0], 1;" :: "l"(ctr) : "memory");
            unsigned int v;
            do {
                asm volatile("ld.acquire.gpu.global.u32 %0, [%1];" : "=r"(v) : "l"(ctr) : "memory");
            } while (v < target);
        }
        __syncthreads();
    }
}

// ---------------- K4: output projection -> emissions [t][b][k] ----------------
__global__ void proj_kernel(const float* __restrict__ w_out, const float* __restrict__ b_out)
{
    int t = blockIdx.x;
    int tid = threadIdx.x;                     // 576 = 9*64
    int b = tid & 63;
    int k = tid >> 6;
    const float* hf = g_h + (size_t)(t + 1) * HB + b;
    const float* hb = g_h + (size_t)(TT + 1) * HB + (size_t)(TT - t) * HB + b;
    const float* w0 = w_out + (size_t)k * (2 * HH);
    float s = b_out[k];
#pragma unroll 4
    for (int j = 0; j < HH; j++) s = fmaf(hf[(size_t)j * BB], w0[j], s);
#pragma unroll 4
    for (int j = 0; j < HH; j++) s = fmaf(hb[(size_t)j * BB], w0[HH + j], s);
    g_emis[(size_t)t * (BB * KKT) + b * KKT + k] = s;
}

// ---------------- K5: Viterbi decode ----------------
__global__ void viterbi_kernel(const float* __restrict__ start_t, const float* __restrict__ end_t,
                               const float* __restrict__ trans, float* __restrict__ out)
{
    int b = blockIdx.x;
    int k = threadIdx.x;
    __shared__ float sc[KKT], ns[KKT], tr[KKT * KKT];
    for (int i = k; i < KKT * KKT; i += 32) tr[i] = trans[i];
    if (k < KKT) sc[k] = start_t[k] + g_emis[(size_t)b * KKT + k];
    __syncwarp();
    for (int t = 1; t < TT; t++) {
        if (k < KKT) {
            float best = -1e30f; int arg = 0;
#pragma unroll
            for (int kp = 0; kp < KKT; kp++) {
                float v = sc[kp] + tr[kp * KKT + k];
                if (v > best) { best = v; arg = kp; }
            }
            ns[k] = best + g_emis[((size_t)t * BB + b) * KKT + k];
            g_hist[((size_t)(t - 1) * BB + b) * KKT + k] = arg;
        }
        __syncwarp();
        if (k < KKT) sc[k] = ns[k];
        __syncwarp();
    }
    if (k == 0) {
        float best = -1e30f; int last = 0;
#pragma unroll
        for (int kk = 0; kk < KKT; kk++) {
            float v = sc[kk] + end_t[kk];
            if (v > best) { best = v; last = kk; }
        }
        out[(size_t)b * TT + (TT - 1)] = (float)last;
        int tag = last;
        for (int t = TT - 2; t >= 0; t--) {
            tag = g_hist[((size_t)t * BB + b) * KKT + tag];
            out[(size_t)b * TT + t] = (float)tag;
        }
    }
}

// ---------------- K6: CRF NLL per batch element ----------------
__global__ void crf_kernel(const int* __restrict__ tags, const float* __restrict__ start_t,
                           const float* __restrict__ end_t, const float* __restrict__ trans)
{
    int b = blockIdx.x;
    int k = threadIdx.x;
    __shared__ float al[KKT], na[KKT], tr[KKT * KKT];
    for (int i = k; i < KKT * KKT; i += 32) tr[i] = trans[i];
    if (k < KKT) al[k] = start_t[k] + g_emis[(size_t)b * KKT + k];
    __syncwarp();
    for (int t = 1; t < TT; t++) {
        if (k < KKT) {
            float mx = -1e30f;
#pragma unroll
            for (int kp = 0; kp < KKT; kp++) mx = fmaxf(mx, al[kp] + tr[kp * KKT + k]);
            float s = 0.f;
#pragma unroll
            for (int kp = 0; kp < KKT; kp++) s += expf(al[kp] + tr[kp * KKT + k] - mx);
            na[k] = mx + logf(s) + g_emis[((size_t)t * BB + b) * KKT + k];
        }
        __syncwarp();
        if (k < KKT) al[k] = na[k];
        __syncwarp();
    }
    if (k == 0) {
        float mx = -1e30f;
#pragma unroll
        for (int kk = 0; kk < KKT; kk++) mx = fmaxf(mx, al[kk] + end_t[kk]);
        float s = 0.f;
#pragma unroll
        for (int kk = 0; kk < KKT; kk++) s += expf(al[kk] + end_t[kk] - mx);
        float den = mx + logf(s);
        int prev = tags[(size_t)b * TT + 0];
        float num = start_t[prev] + g_emis[(size_t)b * KKT + prev];
        for (int t = 1; t < TT; t++) {
            int tt = tags[(size_t)b * TT + t];
            num += tr[prev * KKT + tt] + g_emis[((size_t)t * BB + b) * KKT + tt];
            prev = tt;
        }
        num += end_t[prev];
        g_lossb[b] = den - num;
    }
}

// ---------------- K7: deterministic loss reduction ----------------
__global__ void finalize_kernel(float* __restrict__ out)
{
    if (blockIdx.x == 0 && threadIdx.x == 0) {
        float s = 0.f;
        for (int b = 0; b < BB; b++) s += g_lossb[b];
        out[(size_t)BB * TT] = s;
    }
}

// ---------------- launch ----------------
extern "C" void kernel_launch(void* const* d_in, const int* in_sizes, int n_in,
                              void* d_out, int out_size)
{
    const int*   tokens  = (const int*)  d_in[0];
    const int*   tags    = (const int*)  d_in[1];
    // d_in[2] = mask (all ones by construction; unused)
    const float* emb     = (const float*)d_in[3];
    const float* w_ih_f  = (const float*)d_in[4];
    const float* w_hh_f  = (const float*)d_in[5];
    const float* b_ih_f  = (const float*)d_in[6];
    const float* b_hh_f  = (const float*)d_in[7];
    const float* w_ih_b  = (const float*)d_in[8];
    const float* w_hh_b  = (const float*)d_in[9];
    const float* b_ih_b  = (const float*)d_in[10];
    const float* b_hh_b  = (const float*)d_in[11];
    const float* h0      = (const float*)d_in[12];
    const float* c0      = (const float*)d_in[13];
    const float* w_out   = (const float*)d_in[14];
    const float* b_out   = (const float*)d_in[15];
    const float* start_t = (const float*)d_in[16];
    const float* end_t   = (const float*)d_in[17];
    const float* trans   = (const float*)d_in[18];
    float* out = (float*)d_out;

    const int rec_smem = (304 * 64 + 128 * PSTR) * 4;   // 112640 bytes
    static int smem_set = 0;
    if (!smem_set) {
        cudaFuncSetAttribute(lstm_rec_kernel, cudaFuncAttributeMaxDynamicSharedMemorySize, rec_smem);
        smem_set = 1;
    }

    prep_kernel<<<150, 256>>>(b_ih_f, b_hh_f, b_ih_b, b_hh_b, h0);
    gather_kernel<<<TT, 256>>>(tokens, emb);
    gemm_pre_kernel<<<dim3(NCOL / 128, 19), 256>>>(w_ih_f, w_ih_b);
    lstm_rec_kernel<<<2 * NSL, 256, rec_smem>>>(w_hh_f, w_hh_b, c0);
    proj_kernel<<<TT, 576>>>(w_out, b_out);
    viterbi_kernel<<<BB, 32>>>(start_t, end_t, trans, out);
    crf_kernel<<<BB, 32>>>(tags, start_t, end_t, trans);
    finalize_kernel<<<1, 1>>>(out);
}

// round 7
// speedup vs baseline: 1.4606x; 1.1801x over previous
#include <cuda_runtime.h>
#include <math.h>

// Problem dims
#define TT   512
#define BB   64
#define HH   300
#define KKT  9
#define G4   1200           // 4*H
#define NCOL 32768          // T*B columns (t*64+b)
#define HB   (HH*BB)        // 19200
#define NSL  75             // slices per direction (4 cols each); grid = 150
#define HROW 68             // padded h_sm row stride (floats); bh=1 half at +36
#define PROW 36             // part row stride (floats): 32 data + 4 pad

typedef unsigned long long ull;

// ---------------- scratch (device globals; no runtime allocation) ----------------
__device__ __align__(16) float g_xT[(size_t)HH * NCOL];
__device__ __align__(16) float g_pre[(size_t)2 * G4 * NCOL];
__device__ __align__(16) float g_h[(size_t)2 * (TT + 1) * HB];   // [dir][t+1][k][b]
__device__ float g_emis[(size_t)TT * BB * KKT];
__device__ int   g_hist[(size_t)(TT - 1) * BB * KKT];
__device__ float g_bias[2 * G4];
__device__ float g_lossb[BB];
__device__ unsigned int g_bar2[64];                // [0]=fwd ctr, [32]=bwd ctr

// ---------------- helpers ----------------
__device__ __forceinline__ ull dup2(float v) {
    ull r; asm("mov.b64 %0, {%1, %1};" : "=l"(r) : "f"(v)); return r;
}
__device__ __forceinline__ ull fma2(ull a, ull b, ull c) {
    ull d; asm("fma.rn.f32x2 %0, %1, %2, %3;" : "=l"(d) : "l"(a), "l"(b), "l"(c)); return d;
}
__device__ __forceinline__ float2 u2f(ull v) {
    float2 r; asm("mov.b64 {%0, %1}, %2;" : "=f"(r.x), "=f"(r.y) : "l"(v)); return r;
}
__device__ __forceinline__ float sig_(float x) { return 1.0f / (1.0f + __expf(-x)); }
__device__ __forceinline__ float tanh_(float x) {
    float e = __expf(-2.0f * fabsf(x));
    float r = (1.0f - e) / (1.0f + e);
    return copysignf(r, x);
}
__device__ __forceinline__ unsigned int smem_u32(const void* p) {
    unsigned int a;
    asm("{ .reg .u64 t; cvta.to.shared.u64 t, %1; cvt.u32.u64 %0, t; }" : "=r"(a) : "l"(p));
    return a;
}
__device__ __forceinline__ void cpa16(unsigned int dst, const void* src) {
    asm volatile("cp.async.cg.shared.global [%0], [%1], 16;" :: "r"(dst), "l"(src) : "memory");
}

// ---------------- K0: prep — fused bias, h0 transpose, barrier reset ----------------
__global__ void prep_kernel(const float* __restrict__ b_ih_f, const float* __restrict__ b_hh_f,
                            const float* __restrict__ b_ih_b, const float* __restrict__ b_hh_b,
                            const float* __restrict__ h0)
{
    int idx = blockIdx.x * blockDim.x + threadIdx.x;
    if (idx < 64) g_bar2[idx] = 0u;
    if (idx < 2 * G4) {
        g_bias[idx] = (idx < G4) ? (b_ih_f[idx] + b_hh_f[idx])
                                 : (b_ih_b[idx - G4] + b_hh_b[idx - G4]);
    }
    if (idx < 2 * HB) {
        int dir = idx / HB;
        int rem = idx - dir * HB;
        int k = rem >> 6;
        int b = rem & 63;
        g_h[(size_t)dir * (TT + 1) * HB + (size_t)k * BB + b] = h0[(size_t)(dir * BB + b) * HH + k];
    }
}

// ---------------- K1: embedding gather into transposed layout [d][t*64+b] ----------------
__global__ void gather_kernel(const int* __restrict__ tokens, const float* __restrict__ emb)
{
    int t = blockIdx.x;
    __shared__ int tok[BB];
    if (threadIdx.x < BB) tok[threadIdx.x] = tokens[threadIdx.x * TT + t];
    __syncthreads();
    for (int idx = threadIdx.x; idx < HH * BB; idx += blockDim.x) {
        int d = idx >> 6;
        int b = idx & 63;
        g_xT[(size_t)d * NCOL + (size_t)t * BB + b] = emb[(size_t)tok[b] * HH + d];
    }
}

// ---------------- K2: input projection GEMM (f32x2) ----------------
__global__ void __launch_bounds__(256) gemm_pre_kernel(const float* __restrict__ w_ih_f,
                                                       const float* __restrict__ w_ih_b)
{
    const int M = 2 * G4;
    const int Kd = HH;
    __shared__ __align__(16) ull   As2[8][128];
    __shared__ __align__(16) float Bs[8][128];

    int m0 = blockIdx.y * 128;
    int n0 = blockIdx.x * 128;
    int tid = threadIdx.x;
    int ty = tid >> 4;
    int tx = tid & 15;

    ull acc[8][4];
#pragma unroll
    for (int i = 0; i < 8; i++)
#pragma unroll
        for (int j = 0; j < 4; j++) acc[i][j] = 0ull;

    int lk  = tid & 7;    int lm  = tid >> 3;
    int ln  = tid & 127;  int lkb = tid >> 7;

    for (int k0 = 0; k0 < Kd; k0 += 8) {
#pragma unroll
        for (int p = 0; p < 4; p++) {
            int m = m0 + lm + p * 32;
            int kc = k0 + lk;
            float v = 0.f;
            if (m < M && kc < Kd)
                v = (m < G4) ? w_ih_f[(size_t)m * HH + kc]
                             : w_ih_b[(size_t)(m - G4) * HH + kc];
            As2[lk][lm + p * 32] = dup2(v);
        }
#pragma unroll
        for (int p = 0; p < 4; p++) {
            int kc = k0 + lkb + p * 2;
            Bs[lkb + p * 2][ln] = (kc < Kd) ? g_xT[(size_t)kc * NCOL + n0 + ln] : 0.f;
        }
        __syncthreads();
#pragma unroll
        for (int kk = 0; kk < 8; kk++) {
            ull av[8], bv[4];
#pragma unroll
            for (int i = 0; i < 8; i++) av[i] = As2[kk][ty * 8 + i];
            const ull* bsp = (const ull*)&Bs[kk][0];
#pragma unroll
            for (int j = 0; j < 4; j++) bv[j] = bsp[tx * 4 + j];
#pragma unroll
            for (int i = 0; i < 8; i++)
#pragma unroll
                for (int j = 0; j < 4; j++) acc[i][j] = fma2(av[i], bv[j], acc[i][j]);
        }
        __syncthreads();
    }

#pragma unroll
    for (int i = 0; i < 8; i++) {
        int m = m0 + ty * 8 + i;
        if (m >= M) continue;
        float bvs = g_bias[m];
        float* cp = &g_pre[(size_t)m * NCOL + n0 + tx * 8];
#pragma unroll
        for (int j = 0; j < 4; j++) {
            float2 v = u2f(acc[i][j]);
            *(float2*)(cp + j * 2) = make_float2(v.x + bvs, v.y + bvs);
        }
    }
}

// ---------------- K3: persistent LSTM recurrence v5 ----------------
// grid = 150 (2 dir x 75 slices of 4 cols), 512 threads (16 warps, 4/SMSP).
// Thread (ks 0..15, cgp 0..15, bh 0..1): W (19 dup'd f32x2) in registers.
// Each warp cp.async-stages its own 19 h rows into smem with a 68-float row
// stride (bh=1 half at +36 floats = odd bank granule -> conflict-free LDS.128).
// Partials land in 36-float rows (conflict-free STS.128); 256-thread finalize.
__global__ void __launch_bounds__(512, 1) lstm_rec_kernel(const float* __restrict__ whh_f,
                                                          const float* __restrict__ whh_b,
                                                          const float* __restrict__ c0)
{
    extern __shared__ __align__(16) float sm_f[];
    float* h_sm = sm_f;                        // [304][HROW]   = 82688 B
    float* part = sm_f + 304 * HROW;           // [512][PROW]   = 73728 B

    const int bid = blockIdx.x;
    const int dir = bid & 1;
    const int s   = bid >> 1;                  // 0..74
    const int colbase = s * 4;

    const int tid  = threadIdx.x;
    const int ks   = tid >> 5;                 // 0..15 (19 k each; 16*19=304)
    const int lane = tid & 31;
    const int cgp  = lane >> 1;                // 0..15 -> (c,g)
    const int bh   = lane & 1;                 // batch half
    const int c    = cgp >> 2;
    const int g    = cgp & 3;

    const float* whh = dir ? whh_b : whh_f;

    // zero pad rows 300..303 (ks=15 reads them; never staged; w=0 there)
    if (tid < 4 * HROW) h_sm[300 * HROW + tid] = 0.f;

    // W_hh slice -> registers (duplicated pairs), loaded once per launch
    ull Wr[19];
#pragma unroll
    for (int kk = 0; kk < 19; kk++) {
        int k = ks * 19 + kk;
        float v = (k < 300) ? whh[(size_t)(g * HH + colbase + c) * HH + k] : 0.f;
        Wr[kk] = dup2(v);
    }

    // finalize role (first 256 threads): 1 column per thread
    const int ffc = (tid >> 6) & 3;
    const int ffb = tid & 63;
    const int bhf = ffb >> 5;
    const int bcol = ffb & 31;
    float cst = 0.f;
    if (tid < 256) cst = c0[(size_t)(dir * BB + ffb) * HH + colbase + ffc];

    __syncthreads();

    float*       ghdir  = g_h + (size_t)dir * (TT + 1) * HB;
    const float* predir = g_pre + (size_t)dir * G4 * NCOL;
    unsigned int* ctr   = &g_bar2[dir * 32];

    const int nf4 = ((ks < 15) ? 19 : 15) * 16;            // float4 chunks this warp stages
    const unsigned int hdst0 = smem_u32(h_sm + (size_t)ks * 19 * HROW);
    const float* hbase = h_sm + (size_t)ks * 19 * HROW + bh * 36;
    float* pp = part + (size_t)(ks * 32 + cgp * 2 + bh) * PROW;

    unsigned int target = 0;
    for (int t = 0; t < TT; t++) {
        const int tp = dir ? (TT - 1 - t) : t;

        // prefetch pre-activations for finalize (hidden behind the dot)
        float pre0 = 0.f, pre1 = 0.f, pre2 = 0.f, pre3 = 0.f;
        if (tid < 256) {
            const float* pb = predir + (size_t)tp * BB + ffb;
            pre0 = __ldcg(pb + (size_t)(0 * HH + colbase + ffc) * NCOL);
            pre1 = __ldcg(pb + (size_t)(1 * HH + colbase + ffc) * NCOL);
            pre2 = __ldcg(pb + (size_t)(2 * HH + colbase + ffc) * NCOL);
            pre3 = __ldcg(pb + (size_t)(3 * HH + colbase + ffc) * NCOL);
        }

        // warp-local h staging with padded/split row layout
        const float4* hsrc = (const float4*)(ghdir + (size_t)t * HB) + ks * 19 * 16;
        for (int i = lane; i < nf4; i += 32) {
            unsigned int dst = hdst0 + (i >> 4) * (HROW * 4) + (i & 15) * 16 + ((i & 8) << 1);
            cpa16(dst, hsrc + i);
        }
        asm volatile("cp.async.commit_group;" ::: "memory");
        asm volatile("cp.async.wait_group 0;" ::: "memory");
        __syncwarp();

        // dot: 19 k x 32 batch for this thread's (col,gate); W in registers
        ull acc[16];
#pragma unroll
        for (int i = 0; i < 16; i++) acc[i] = 0ull;
#pragma unroll
        for (int kk = 0; kk < 19; kk++) {
            const ulonglong2* hp = (const ulonglong2*)(hbase + kk * HROW);
            ull w = Wr[kk];
            ulonglong2 p0 = hp[0], p1 = hp[1], p2 = hp[2], p3 = hp[3];
            acc[0] = fma2(w, p0.x, acc[0]);  acc[1] = fma2(w, p0.y, acc[1]);
            acc[2] = fma2(w, p1.x, acc[2]);  acc[3] = fma2(w, p1.y, acc[3]);
            acc[4] = fma2(w, p2.x, acc[4]);  acc[5] = fma2(w, p2.y, acc[5]);
            acc[6] = fma2(w, p3.x, acc[6]);  acc[7] = fma2(w, p3.y, acc[7]);
            ulonglong2 p4 = hp[4], p5 = hp[5], p6 = hp[6], p7 = hp[7];
            acc[8]  = fma2(w, p4.x, acc[8]);  acc[9]  = fma2(w, p4.y, acc[9]);
            acc[10] = fma2(w, p5.x, acc[10]); acc[11] = fma2(w, p5.y, acc[11]);
            acc[12] = fma2(w, p6.x, acc[12]); acc[13] = fma2(w, p6.y, acc[13]);
            acc[14] = fma2(w, p7.x, acc[14]); acc[15] = fma2(w, p7.y, acc[15]);
        }

        // store partials (conflict-free: 36-float row stride)
#pragma unroll
        for (int j = 0; j < 8; j++) {
            ulonglong2 v; v.x = acc[2 * j]; v.y = acc[2 * j + 1];
            *(ulonglong2*)(pp + j * 4) = v;
        }
        __syncthreads();

        // finalize: sum 16 k-partials + pre, gates, write h(t+1)
        if (tid < 256) {
            float gv0 = pre0, gv1 = pre1, gv2 = pre2, gv3 = pre3;
#pragma unroll
            for (int kss = 0; kss < 16; kss++) {
                const float* pr = part + (size_t)(kss * 32 + ffc * 8 + bhf) * PROW + bcol;
                gv0 += pr[0];
                gv1 += pr[2 * PROW];
                gv2 += pr[4 * PROW];
                gv3 += pr[6 * PROW];
            }
            float ig = sig_(gv0), fg = sig_(gv1), gt = tanh_(gv2), og = sig_(gv3);
            cst = fg * cst + ig * gt;
            ghdir[(size_t)(t + 1) * HB + (size_t)(colbase + ffc) * BB + ffb] = og * tanh_(cst);
        }

        // per-direction grid barrier: release-arrive + acquire-poll
        target += NSL;
        __syncthreads();
        if (tid == 0) {
            asm volatile("red.release.gpu.global.add.u32 [%0], 1;" :: "l"(ctr) : "memory");
            unsigned int v;
            do {
                asm volatile("ld.acquire.gpu.global.u32 %0, [%1];" : "=r"(v) : "l"(ctr) : "memory");
            } while (v < target);
        }
        __syncthreads();
    }
}

// ---------------- K4: output projection -> emissions [t][b][k] ----------------
__global__ void proj_kernel(const float* __restrict__ w_out, const float* __restrict__ b_out)
{
    int t = blockIdx.x;
    int tid = threadIdx.x;                     // 576 = 9*64
    int b = tid & 63;
    int k = tid >> 6;
    const float* hf = g_h + (size_t)(t + 1) * HB + b;
    const float* hb = g_h + (size_t)(TT + 1) * HB + (size_t)(TT - t) * HB + b;
    const float* w0 = w_out + (size_t)k * (2 * HH);
    float s = b_out[k];
#pragma unroll 4
    for (int j = 0; j < HH; j++) s = fmaf(hf[(size_t)j * BB], w0[j], s);
#pragma unroll 4
    for (int j = 0; j < HH; j++) s = fmaf(hb[(size_t)j * BB], w0[HH + j], s);
    g_emis[(size_t)t * (BB * KKT) + b * KKT + k] = s;
}

// ---------------- K5: Viterbi decode ----------------
__global__ void viterbi_kernel(const float* __restrict__ start_t, const float* __restrict__ end_t,
                               const float* __restrict__ trans, float* __restrict__ out)
{
    int b = blockIdx.x;
    int k = threadIdx.x;
    __shared__ float sc[KKT], ns[KKT], tr[KKT * KKT];
    for (int i = k; i < KKT * KKT; i += 32) tr[i] = trans[i];
    if (k < KKT) sc[k] = start_t[k] + g_emis[(size_t)b * KKT + k];
    __syncwarp();
    for (int t = 1; t < TT; t++) {
        if (k < KKT) {
            float best = -1e30f; int arg = 0;
#pragma unroll
            for (int kp = 0; kp < KKT; kp++) {
                float v = sc[kp] + tr[kp * KKT + k];
                if (v > best) { best = v; arg = kp; }
            }
            ns[k] = best + g_emis[((size_t)t * BB + b) * KKT + k];
            g_hist[((size_t)(t - 1) * BB + b) * KKT + k] = arg;
        }
        __syncwarp();
        if (k < KKT) sc[k] = ns[k];
        __syncwarp();
    }
    if (k == 0) {
        float best = -1e30f; int last = 0;
#pragma unroll
        for (int kk = 0; kk < KKT; kk++) {
            float v = sc[kk] + end_t[kk];
            if (v > best) { best = v; last = kk; }
        }
        out[(size_t)b * TT + (TT - 1)] = (float)last;
        int tag = last;
        for (int t = TT - 2; t >= 0; t--) {
            tag = g_hist[((size_t)t * BB + b) * KKT + tag];
            out[(size_t)b * TT + t] = (float)tag;
        }
    }
}

// ---------------- K6: CRF NLL per batch element ----------------
__global__ void crf_kernel(const int* __restrict__ tags, const float* __restrict__ start_t,
                           const float* __restrict__ end_t, const float* __restrict__ trans)
{
    int b = blockIdx.x;
    int k = threadIdx.x;
    __shared__ float al[KKT], na[KKT], tr[KKT * KKT];
    for (int i = k; i < KKT * KKT; i += 32) tr[i] = trans[i];
    if (k < KKT) al[k] = start_t[k] + g_emis[(size_t)b * KKT + k];
    __syncwarp();
    for (int t = 1; t < TT; t++) {
        if (k < KKT) {
            float mx = -1e30f;
#pragma unroll
            for (int kp = 0; kp < KKT; kp++) mx = fmaxf(mx, al[kp] + tr[kp * KKT + k]);
            float s = 0.f;
#pragma unroll
            for (int kp = 0; kp < KKT; kp++) s += expf(al[kp] + tr[kp * KKT + k] - mx);
            na[k] = mx + logf(s) + g_emis[((size_t)t * BB + b) * KKT + k];
        }
        __syncwarp();
        if (k < KKT) al[k] = na[k];
        __syncwarp();
    }
    if (k == 0) {
        float mx = -1e30f;
#pragma unroll
        for (int kk = 0; kk < KKT; kk++) mx = fmaxf(mx, al[kk] + end_t[kk]);
        float s = 0.f;
#pragma unroll
        for (int kk = 0; kk < KKT; kk++) s += expf(al[kk] + end_t[kk] - mx);
        float den = mx + logf(s);
        int prev = tags[(size_t)b * TT + 0];
        float num = start_t[prev] + g_emis[(size_t)b * KKT + prev];
        for (int t = 1; t < TT; t++) {
            int tt = tags[(size_t)b * TT + t];
            num += tr[prev * KKT + tt] + g_emis[((size_t)t * BB + b) * KKT + tt];
            prev = tt;
        }
        num += end_t[prev];
        g_lossb[b] = den - num;
    }
}

// ---------------- K7: deterministic loss reduction ----------------
__global__ void finalize_kernel(float* __restrict__ out)
{
    if (blockIdx.x == 0 && threadIdx.x == 0) {
        float s = 0.f;
        for (int b = 0; b < BB; b++) s += g_lossb[b];
        out[(size_t)BB * TT] = s;
    }
}

// ---------------- launch ----------------
extern "C" void kernel_launch(void* const* d_in, const int* in_sizes, int n_in,
                              void* d_out, int out_size)
{
    const int*   tokens  = (const int*)  d_in[0];
    const int*   tags    = (const int*)  d_in[1];
    // d_in[2] = mask (all ones by construction; unused)
    const float* emb     = (const float*)d_in[3];
    const float* w_ih_f  = (const float*)d_in[4];
    const float* w_hh_f  = (const float*)d_in[5];
    const float* b_ih_f  = (const float*)d_in[6];
    const float* b_hh_f  = (const float*)d_in[7];
    const float* w_ih_b  = (const float*)d_in[8];
    const float* w_hh_b  = (const float*)d_in[9];
    const float* b_ih_b  = (const float*)d_in[10];
    const float* b_hh_b  = (const float*)d_in[11];
    const float* h0      = (const float*)d_in[12];
    const float* c0      = (const float*)d_in[13];
    const float* w_out   = (const float*)d_in[14];
    const float* b_out   = (const float*)d_in[15];
    const float* start_t = (const float*)d_in[16];
    const float* end_t   = (const float*)d_in[17];
    const float* trans   = (const float*)d_in[18];
    float* out = (float*)d_out;

    const int rec_smem = (304 * HROW + 512 * PROW) * 4;   // 156416 bytes
    static int smem_set = 0;
    if (!smem_set) {
        cudaFuncSetAttribute(lstm_rec_kernel, cudaFuncAttributeMaxDynamicSharedMemorySize, rec_smem);
        smem_set = 1;
    }

    prep_kernel<<<150, 256>>>(b_ih_f, b_hh_f, b_ih_b, b_hh_b, h0);
    gather_kernel<<<TT, 256>>>(tokens, emb);
    gemm_pre_kernel<<<dim3(NCOL / 128, 19), 256>>>(w_ih_f, w_ih_b);
    lstm_rec_kernel<<<2 * NSL, 512, rec_smem>>>(w_hh_f, w_hh_b, c0);
    proj_kernel<<<TT, 576>>>(w_out, b_out);
    viterbi_kernel<<<BB, 32>>>(start_t, end_t, trans, out);
    crf_kernel<<<BB, 32>>>(tags, start_t, end_t, trans);
    finalize_kernel<<<1, 1>>>(out);
}

// round 8
// speedup vs baseline: 1.9511x; 1.3359x over previous
#include <cuda_runtime.h>
#include <math.h>

// Problem dims
#define TT   512
#define BB   64
#define HH   300
#define KKT  9
#define G4   1200           // 4*H
#define NCOL 32768          // T*B columns (t*64+b)
#define HB   (HH*BB)        // 19200
#define NSL  75             // slices per direction (4 cols each); grid = 150
#define HROW 68             // padded h_sm row stride (floats); batch quads at {0,16,36,52}
#define PROW 68             // part row stride (floats), same quad layout

typedef unsigned long long ull;

// ---------------- scratch (device globals; no runtime allocation) ----------------
__device__ __align__(16) float g_xT[(size_t)HH * NCOL];
__device__ __align__(16) float g_pre[(size_t)2 * G4 * NCOL];
__device__ __align__(16) float g_h[(size_t)2 * (TT + 1) * HB];   // [dir][t+1][k][b]
__device__ float g_emis[(size_t)TT * BB * KKT];
__device__ int   g_hist[(size_t)(TT - 1) * BB * KKT];
__device__ float g_bias[2 * G4];
__device__ float g_lossb[BB];
__device__ unsigned int g_bar2[64];                // [0]=fwd ctr, [32]=bwd ctr

// ---------------- helpers ----------------
__device__ __forceinline__ ull dup2(float v) {
    ull r; asm("mov.b64 %0, {%1, %1};" : "=l"(r) : "f"(v)); return r;
}
__device__ __forceinline__ ull fma2(ull a, ull b, ull c) {
    ull d; asm("fma.rn.f32x2 %0, %1, %2, %3;" : "=l"(d) : "l"(a), "l"(b), "l"(c)); return d;
}
__device__ __forceinline__ float2 u2f(ull v) {
    float2 r; asm("mov.b64 {%0, %1}, %2;" : "=f"(r.x), "=f"(r.y) : "l"(v)); return r;
}
__device__ __forceinline__ float sig_(float x) { return 1.0f / (1.0f + __expf(-x)); }
__device__ __forceinline__ float tanh_(float x) {
    float e = __expf(-2.0f * fabsf(x));
    float r = (1.0f - e) / (1.0f + e);
    return copysignf(r, x);
}
__device__ __forceinline__ unsigned int smem_u32(const void* p) {
    unsigned int a;
    asm("{ .reg .u64 t; cvta.to.shared.u64 t, %1; cvt.u32.u64 %0, t; }" : "=r"(a) : "l"(p));
    return a;
}
__device__ __forceinline__ void cpa16(unsigned int dst, const void* src) {
    asm volatile("cp.async.cg.shared.global [%0], [%1], 16;" :: "r"(dst), "l"(src) : "memory");
}
__device__ __forceinline__ void cpa16z(unsigned int dst, const void* src, int srcbytes) {
    asm volatile("cp.async.cg.shared.global [%0], [%1], 16, %2;"
                 :: "r"(dst), "l"(src), "r"(srcbytes) : "memory");
}

// ---------------- K0: prep ----------------
__global__ void prep_kernel(const float* __restrict__ b_ih_f, const float* __restrict__ b_hh_f,
                            const float* __restrict__ b_ih_b, const float* __restrict__ b_hh_b,
                            const float* __restrict__ h0)
{
    int idx = blockIdx.x * blockDim.x + threadIdx.x;
    if (idx < 64) g_bar2[idx] = 0u;
    if (idx < 2 * G4) {
        g_bias[idx] = (idx < G4) ? (b_ih_f[idx] + b_hh_f[idx])
                                 : (b_ih_b[idx - G4] + b_hh_b[idx - G4]);
    }
    if (idx < 2 * HB) {
        int dir = idx / HB;
        int rem = idx - dir * HB;
        int k = rem >> 6;
        int b = rem & 63;
        g_h[(size_t)dir * (TT + 1) * HB + (size_t)k * BB + b] = h0[(size_t)(dir * BB + b) * HH + k];
    }
}

// ---------------- K1: embedding gather ----------------
__global__ void gather_kernel(const int* __restrict__ tokens, const float* __restrict__ emb)
{
    int t = blockIdx.x;
    __shared__ int tok[BB];
    if (threadIdx.x < BB) tok[threadIdx.x] = tokens[threadIdx.x * TT + t];
    __syncthreads();
    for (int idx = threadIdx.x; idx < HH * BB; idx += blockDim.x) {
        int d = idx >> 6;
        int b = idx & 63;
        g_xT[(size_t)d * NCOL + (size_t)t * BB + b] = emb[(size_t)tok[b] * HH + d];
    }
}

// ---------------- K2: input projection GEMM v2 (f32x2, 2-stage cp.async pipeline) ----------------
#define BK 16
#define NCH 19                        // ceil(300/16)
__global__ void __launch_bounds__(256, 2) gemm_pre_kernel(const float* __restrict__ w_ih_f,
                                                          const float* __restrict__ w_ih_b)
{
    __shared__ __align__(16) ull   As2[2][BK][128];   // dup'd A, k-major   32KB
    __shared__ __align__(16) float Bs[2][BK][128];    //                    16KB

    const int m0 = blockIdx.y * 128;
    const int n0 = blockIdx.x * 128;
    const int tid = threadIdx.x;
    const int ty = tid >> 4;          // 0..15: m rows ty*8..+7
    const int tx = tid & 15;          // n cols {tx*4..+3, 64+tx*4..+3}

    // A loader role: row lm, k-offset ka (0 or 8)
    const int lm = tid & 127;
    const int ka = (tid >> 7) * 8;
    const int am = m0 + lm;
    const bool amv = (am < 2400);
    const float* wrow = amv ? ((am < G4) ? (w_ih_f + (size_t)am * HH)
                                         : (w_ih_b + (size_t)(am - G4) * HH)) : (const float*)w_ih_f;

    // B loader role: 2 rows kb*2, kb*2+1; cols nb..nb+3
    const int nb = (tid & 31) * 4;
    const int kb = tid >> 5;          // 0..7

    ull acc[8][4];
#pragma unroll
    for (int i = 0; i < 8; i++)
#pragma unroll
        for (int j = 0; j < 4; j++) acc[i][j] = 0ull;

    float4 a0, a1;
    // ---- prologue: chunk 0 ----
    {
        int k0 = 0;
        a0 = amv ? *(const float4*)(wrow + k0 + ka) : make_float4(0, 0, 0, 0);
        a1 = amv ? *(const float4*)(wrow + k0 + ka + 4) : make_float4(0, 0, 0, 0);
#pragma unroll
        for (int r = 0; r < 2; r++) {
            int kc = k0 + kb * 2 + r;
            cpa16z(smem_u32(&Bs[0][kb * 2 + r][nb]),
                   g_xT + (size_t)kc * NCOL + n0 + nb, (kc < 300) ? 16 : 0);
        }
        asm volatile("cp.async.commit_group;" ::: "memory");
        As2[0][ka + 0][lm] = dup2(a0.x); As2[0][ka + 1][lm] = dup2(a0.y);
        As2[0][ka + 2][lm] = dup2(a0.z); As2[0][ka + 3][lm] = dup2(a0.w);
        As2[0][ka + 4][lm] = dup2(a1.x); As2[0][ka + 5][lm] = dup2(a1.y);
        As2[0][ka + 6][lm] = dup2(a1.z); As2[0][ka + 7][lm] = dup2(a1.w);
        asm volatile("cp.async.wait_group 0;" ::: "memory");
        __syncthreads();
    }

    int buf = 0;
    for (int ch = 1; ch < NCH; ch++) {
        const int k0 = ch * BK;
        // issue next A (regs) + next B (cp.async) into buf^1
        bool v0 = amv && (k0 + ka + 3 < 300);
        bool v1 = amv && (k0 + ka + 7 < 300);
        a0 = v0 ? *(const float4*)(wrow + k0 + ka) : make_float4(0, 0, 0, 0);
        a1 = v1 ? *(const float4*)(wrow + k0 + ka + 4) : make_float4(0, 0, 0, 0);
#pragma unroll
        for (int r = 0; r < 2; r++) {
            int kc = k0 + kb * 2 + r;
            cpa16z(smem_u32(&Bs[buf ^ 1][kb * 2 + r][nb]),
                   g_xT + (size_t)kc * NCOL + n0 + nb, (kc < 300) ? 16 : 0);
        }
        asm volatile("cp.async.commit_group;" ::: "memory");

        // compute current buffer
#pragma unroll
        for (int kk = 0; kk < BK; kk++) {
            ull av[8];
            const ull* ap = &As2[buf][kk][ty * 8];
#pragma unroll
            for (int i = 0; i < 8; i++) av[i] = ap[i];
            ulonglong2 b0 = *(const ulonglong2*)&Bs[buf][kk][tx * 4];
            ulonglong2 b1 = *(const ulonglong2*)&Bs[buf][kk][64 + tx * 4];
#pragma unroll
            for (int i = 0; i < 8; i++) {
                acc[i][0] = fma2(av[i], b0.x, acc[i][0]);
                acc[i][1] = fma2(av[i], b0.y, acc[i][1]);
                acc[i][2] = fma2(av[i], b1.x, acc[i][2]);
                acc[i][3] = fma2(av[i], b1.y, acc[i][3]);
            }
        }
        // store A regs into next buffer
        As2[buf ^ 1][ka + 0][lm] = dup2(a0.x); As2[buf ^ 1][ka + 1][lm] = dup2(a0.y);
        As2[buf ^ 1][ka + 2][lm] = dup2(a0.z); As2[buf ^ 1][ka + 3][lm] = dup2(a0.w);
        As2[buf ^ 1][ka + 4][lm] = dup2(a1.x); As2[buf ^ 1][ka + 5][lm] = dup2(a1.y);
        As2[buf ^ 1][ka + 6][lm] = dup2(a1.z); As2[buf ^ 1][ka + 7][lm] = dup2(a1.w);
        asm volatile("cp.async.wait_group 0;" ::: "memory");
        __syncthreads();
        buf ^= 1;
    }
    // tail compute
#pragma unroll
    for (int kk = 0; kk < BK; kk++) {
        ull av[8];
        const ull* ap = &As2[buf][kk][ty * 8];
#pragma unroll
        for (int i = 0; i < 8; i++) av[i] = ap[i];
        ulonglong2 b0 = *(const ulonglong2*)&Bs[buf][kk][tx * 4];
        ulonglong2 b1 = *(const ulonglong2*)&Bs[buf][kk][64 + tx * 4];
#pragma unroll
        for (int i = 0; i < 8; i++) {
            acc[i][0] = fma2(av[i], b0.x, acc[i][0]);
            acc[i][1] = fma2(av[i], b0.y, acc[i][1]);
            acc[i][2] = fma2(av[i], b1.x, acc[i][2]);
            acc[i][3] = fma2(av[i], b1.y, acc[i][3]);
        }
    }

    // epilogue: + bias, write
#pragma unroll
    for (int i = 0; i < 8; i++) {
        int m = m0 + ty * 8 + i;
        if (m >= 2400) continue;
        float bvs = g_bias[m];
        float2 v0 = u2f(acc[i][0]), v1 = u2f(acc[i][1]);
        float2 v2 = u2f(acc[i][2]), v3 = u2f(acc[i][3]);
        float* cp = &g_pre[(size_t)m * NCOL + n0];
        *(float4*)(cp + tx * 4)      = make_float4(v0.x + bvs, v0.y + bvs, v1.x + bvs, v1.y + bvs);
        *(float4*)(cp + 64 + tx * 4) = make_float4(v2.x + bvs, v2.y + bvs, v3.x + bvs, v3.y + bvs);
    }
}

// ---------------- K3: persistent LSTM recurrence v6 ----------------
// grid = 150 (2 dir x 75 slices of 4 cols), 512 threads (16 warps).
// Warp = ks (19 k each). Lane = bq*8 + cgrp: thread owns 2 (c,g) pairs
// (cgrp, cgrp+8) x 16 batch (quad bq) x 19 k. One h load feeds both cgs
// (register reuse halves dot LDS). All smem phases bank-conflict-free.
__global__ void __launch_bounds__(512, 1) lstm_rec_kernel(const float* __restrict__ whh_f,
                                                          const float* __restrict__ whh_b,
                                                          const float* __restrict__ c0)
{
    extern __shared__ __align__(16) float sm_f[];
    float* h_sm = sm_f;                        // [304][HROW]
    float* part = sm_f + 304 * HROW;           // [256][PROW]  (16ks x 16cg)

    const int bid = blockIdx.x;
    const int dir = bid & 1;
    const int s   = bid >> 1;                  // 0..74
    const int colbase = s * 4;

    const int tid  = threadIdx.x;
    const int ks   = tid >> 5;                 // 0..15 (19 k each)
    const int lane = tid & 31;
    const int bq   = lane >> 3;                // 0..3 batch quad (16 each)
    const int cgrp = lane & 7;                 // owns cg = cgrp, cgrp+8
    const int bqf  = (bq < 2) ? bq * 16 : 36 + (bq - 2) * 16;  // {0,16,36,52}

    const float* whh = dir ? whh_b : whh_f;

    // zero pad rows 300..303
    if (tid < 4 * HROW) h_sm[300 * HROW + tid] = 0.f;

    // W_hh -> registers (fp32; dup'd per use on ALU pipe)
    const int cgA = cgrp,      cA = cgA >> 2, gA = cgA & 3;
    const int cgB = cgrp + 8,  cB = cgB >> 2, gB = cgB & 3;
    float WfA[19], WfB[19];
#pragma unroll
    for (int kk = 0; kk < 19; kk++) {
        int k = ks * 19 + kk;
        WfA[kk] = (k < 300) ? whh[(size_t)(gA * HH + colbase + cA) * HH + k] : 0.f;
        WfB[kk] = (k < 300) ? whh[(size_t)(gB * HH + colbase + cB) * HH + k] : 0.f;
    }

    // finalize role (first 256 threads): 1 column per thread
    const int ffc = (tid >> 6) & 3;
    const int ffb = tid & 63;
    const int fcol = (ffb < 32) ? ffb : ffb + 4;
    float cst = 0.f;
    if (tid < 256) cst = c0[(size_t)(dir * BB + ffb) * HH + colbase + ffc];

    __syncthreads();

    float*       ghdir  = g_h + (size_t)dir * (TT + 1) * HB;
    const float* predir = g_pre + (size_t)dir * G4 * NCOL;
    unsigned int* ctr   = &g_bar2[dir * 32];

    const int nf4 = ((ks < 15) ? 19 : 15) * 16;
    const unsigned int hdst0 = smem_u32(h_sm + (size_t)ks * 19 * HROW);
    const float* hbase = h_sm + (size_t)ks * 19 * HROW + bqf;
    float* ppA = part + (size_t)(ks * 16 + cgA) * PROW + bqf;
    float* ppB = part + (size_t)(ks * 16 + cgB) * PROW + bqf;

    unsigned int target = 0;
    for (int t = 0; t < TT; t++) {
        const int tp = dir ? (TT - 1 - t) : t;

        // prefetch pre-activations for finalize
        float pre0 = 0.f, pre1 = 0.f, pre2 = 0.f, pre3 = 0.f;
        if (tid < 256) {
            const float* pb = predir + (size_t)tp * BB + ffb;
            pre0 = __ldcg(pb + (size_t)(0 * HH + colbase + ffc) * NCOL);
            pre1 = __ldcg(pb + (size_t)(1 * HH + colbase + ffc) * NCOL);
            pre2 = __ldcg(pb + (size_t)(2 * HH + colbase + ffc) * NCOL);
            pre3 = __ldcg(pb + (size_t)(3 * HH + colbase + ffc) * NCOL);
        }

        // warp-local h staging (padded/split row layout)
        const float4* hsrc = (const float4*)(ghdir + (size_t)t * HB) + ks * 19 * 16;
        for (int i = lane; i < nf4; i += 32) {
            unsigned int dst = hdst0 + (i >> 4) * (HROW * 4) + (i & 15) * 16 + ((i & 8) << 1);
            cpa16(dst, hsrc + i);
        }
        asm volatile("cp.async.commit_group;" ::: "memory");
        asm volatile("cp.async.wait_group 0;" ::: "memory");
        __syncwarp();

        // dot: 19 k x 16 batch x 2 (c,g); h loaded once, reused for both cgs
        ull accA[8], accB[8];
#pragma unroll
        for (int i = 0; i < 8; i++) { accA[i] = 0ull; accB[i] = 0ull; }
#pragma unroll
        for (int kk = 0; kk < 19; kk++) {
            const ulonglong2* hp = (const ulonglong2*)(hbase + kk * HROW);
            ulonglong2 q0 = hp[0], q1 = hp[1], q2 = hp[2], q3 = hp[3];
            ull wA = dup2(WfA[kk]);
            ull wB = dup2(WfB[kk]);
            accA[0] = fma2(wA, q0.x, accA[0]); accA[1] = fma2(wA, q0.y, accA[1]);
            accA[2] = fma2(wA, q1.x, accA[2]); accA[3] = fma2(wA, q1.y, accA[3]);
            accA[4] = fma2(wA, q2.x, accA[4]); accA[5] = fma2(wA, q2.y, accA[5]);
            accA[6] = fma2(wA, q3.x, accA[6]); accA[7] = fma2(wA, q3.y, accA[7]);
            accB[0] = fma2(wB, q0.x, accB[0]); accB[1] = fma2(wB, q0.y, accB[1]);
            accB[2] = fma2(wB, q1.x, accB[2]); accB[3] = fma2(wB, q1.y, accB[3]);
            accB[4] = fma2(wB, q2.x, accB[4]); accB[5] = fma2(wB, q2.y, accB[5]);
            accB[6] = fma2(wB, q3.x, accB[6]); accB[7] = fma2(wB, q3.y, accB[7]);
        }

        // store partials (conflict-free by lane=bq*8+cgrp construction)
#pragma unroll
        for (int j = 0; j < 4; j++) {
            ulonglong2 v; v.x = accA[2 * j]; v.y = accA[2 * j + 1];
            *(ulonglong2*)(ppA + j * 4) = v;
        }
#pragma unroll
        for (int j = 0; j < 4; j++) {
            ulonglong2 v; v.x = accB[2 * j]; v.y = accB[2 * j + 1];
            *(ulonglong2*)(ppB + j * 4) = v;
        }
        __syncthreads();

        // finalize: sum 16 ks-partials + pre, gates, write h(t+1)
        if (tid < 256) {
            float gv0 = pre0, gv1 = pre1, gv2 = pre2, gv3 = pre3;
#pragma unroll
            for (int kss = 0; kss < 16; kss++) {
                const float* pr = part + (size_t)(kss * 16 + ffc * 4) * PROW + fcol;
                gv0 += pr[0];
                gv1 += pr[PROW];
                gv2 += pr[2 * PROW];
                gv3 += pr[3 * PROW];
            }
            float ig = sig_(gv0), fg = sig_(gv1), gt = tanh_(gv2), og = sig_(gv3);
            cst = fg * cst + ig * gt;
            ghdir[(size_t)(t + 1) * HB + (size_t)(colbase + ffc) * BB + ffb] = og * tanh_(cst);
        }

        // per-direction grid barrier
        target += NSL;
        __syncthreads();
        if (tid == 0) {
            asm volatile("red.release.gpu.global.add.u32 [%0], 1;" :: "l"(ctr) : "memory");
            unsigned int v;
            do {
                asm volatile("ld.acquire.gpu.global.u32 %0, [%1];" : "=r"(v) : "l"(ctr) : "memory");
            } while (v < target);
        }
        __syncthreads();
    }
}

// ---------------- K4: output projection -> emissions [t][b][k] ----------------
__global__ void proj_kernel(const float* __restrict__ w_out, const float* __restrict__ b_out)
{
    int t = blockIdx.x;
    int tid = threadIdx.x;                     // 576 = 9*64
    int b = tid & 63;
    int k = tid >> 6;
    const float* hf = g_h + (size_t)(t + 1) * HB + b;
    const float* hb = g_h + (size_t)(TT + 1) * HB + (size_t)(TT - t) * HB + b;
    const float* w0 = w_out + (size_t)k * (2 * HH);
    float s = b_out[k];
#pragma unroll 4
    for (int j = 0; j < HH; j++) s = fmaf(hf[(size_t)j * BB], w0[j], s);
#pragma unroll 4
    for (int j = 0; j < HH; j++) s = fmaf(hb[(size_t)j * BB], w0[HH + j], s);
    g_emis[(size_t)t * (BB * KKT) + b * KKT + k] = s;
}

// ---------------- K5: Viterbi decode ----------------
__global__ void viterbi_kernel(const float* __restrict__ start_t, const float* __restrict__ end_t,
                               const float* __restrict__ trans, float* __restrict__ out)
{
    int b = blockIdx.x;
    int k = threadIdx.x;
    __shared__ float sc[KKT], ns[KKT], tr[KKT * KKT];
    for (int i = k; i < KKT * KKT; i += 32) tr[i] = trans[i];
    if (k < KKT) sc[k] = start_t[k] + g_emis[(size_t)b * KKT + k];
    __syncwarp();
    for (int t = 1; t < TT; t++) {
        if (k < KKT) {
            float best = -1e30f; int arg = 0;
#pragma unroll
            for (int kp = 0; kp < KKT; kp++) {
                float v = sc[kp] + tr[kp * KKT + k];
                if (v > best) { best = v; arg = kp; }
            }
            ns[k] = best + g_emis[((size_t)t * BB + b) * KKT + k];
            g_hist[((size_t)(t - 1) * BB + b) * KKT + k] = arg;
        }
        __syncwarp();
        if (k < KKT) sc[k] = ns[k];
        __syncwarp();
    }
    if (k == 0) {
        float best = -1e30f; int last = 0;
#pragma unroll
        for (int kk = 0; kk < KKT; kk++) {
            float v = sc[kk] + end_t[kk];
            if (v > best) { best = v; last = kk; }
        }
        out[(size_t)b * TT + (TT - 1)] = (float)last;
        int tag = last;
        for (int t = TT - 2; t >= 0; t--) {
            tag = g_hist[((size_t)t * BB + b) * KKT + tag];
            out[(size_t)b * TT + t] = (float)tag;
        }
    }
}

// ---------------- K6: CRF NLL per batch element ----------------
__global__ void crf_kernel(const int* __restrict__ tags, const float* __restrict__ start_t,
                           const float* __restrict__ end_t, const float* __restrict__ trans)
{
    int b = blockIdx.x;
    int k = threadIdx.x;
    __shared__ float al[KKT], na[KKT], tr[KKT * KKT];
    for (int i = k; i < KKT * KKT; i += 32) tr[i] = trans[i];
    if (k < KKT) al[k] = start_t[k] + g_emis[(size_t)b * KKT + k];
    __syncwarp();
    for (int t = 1; t < TT; t++) {
        if (k < KKT) {
            float mx = -1e30f;
#pragma unroll
            for (int kp = 0; kp < KKT; kp++) mx = fmaxf(mx, al[kp] + tr[kp * KKT + k]);
            float s = 0.f;
#pragma unroll
            for (int kp = 0; kp < KKT; kp++) s += expf(al[kp] + tr[kp * KKT + k] - mx);
            na[k] = mx + logf(s) + g_emis[((size_t)t * BB + b) * KKT + k];
        }
        __syncwarp();
        if (k < KKT) al[k] = na[k];
        __syncwarp();
    }
    if (k == 0) {
        float mx = -1e30f;
#pragma unroll
        for (int kk = 0; kk < KKT; kk++) mx = fmaxf(mx, al[kk] + end_t[kk]);
        float s = 0.f;
#pragma unroll
        for (int kk = 0; kk < KKT; kk++) s += expf(al[kk] + end_t[kk] - mx);
        float den = mx + logf(s);
        int prev = tags[(size_t)b * TT + 0];
        float num = start_t[prev] + g_emis[(size_t)b * KKT + prev];
        for (int t = 1; t < TT; t++) {
            int tt = tags[(size_t)b * TT + t];
            num += tr[prev * KKT + tt] + g_emis[((size_t)t * BB + b) * KKT + tt];
            prev = tt;
        }
        num += end_t[prev];
        g_lossb[b] = den - num;
    }
}

// ---------------- K7: deterministic loss reduction ----------------
__global__ void finalize_kernel(float* __restrict__ out)
{
    if (blockIdx.x == 0 && threadIdx.x == 0) {
        float s = 0.f;
        for (int b = 0; b < BB; b++) s += g_lossb[b];
        out[(size_t)BB * TT] = s;
    }
}

// ---------------- launch ----------------
extern "C" void kernel_launch(void* const* d_in, const int* in_sizes, int n_in,
                              void* d_out, int out_size)
{
    const int*   tokens  = (const int*)  d_in[0];
    const int*   tags    = (const int*)  d_in[1];
    // d_in[2] = mask (all ones by construction; unused)
    const float* emb     = (const float*)d_in[3];
    const float* w_ih_f  = (const float*)d_in[4];
    const float* w_hh_f  = (const float*)d_in[5];
    const float* b_ih_f  = (const float*)d_in[6];
    const float* b_hh_f  = (const float*)d_in[7];
    const float* w_ih_b  = (const float*)d_in[8];
    const float* w_hh_b  = (const float*)d_in[9];
    const float* b_ih_b  = (const float*)d_in[10];
    const float* b_hh_b  = (const float*)d_in[11];
    const float* h0      = (const float*)d_in[12];
    const float* c0      = (const float*)d_in[13];
    const float* w_out   = (const float*)d_in[14];
    const float* b_out   = (const float*)d_in[15];
    const float* start_t = (const float*)d_in[16];
    const float* end_t   = (const float*)d_in[17];
    const float* trans   = (const float*)d_in[18];
    float* out = (float*)d_out;

    const int rec_smem = (304 * HROW + 256 * PROW) * 4;   // 152320 bytes
    static int smem_set = 0;
    if (!smem_set) {
        cudaFuncSetAttribute(lstm_rec_kernel, cudaFuncAttributeMaxDynamicSharedMemorySize, rec_smem);
        smem_set = 1;
    }

    prep_kernel<<<150, 256>>>(b_ih_f, b_hh_f, b_ih_b, b_hh_b, h0);
    gather_kernel<<<TT, 256>>>(tokens, emb);
    gemm_pre_kernel<<<dim3(NCOL / 128, 19), 256>>>(w_ih_f, w_ih_b);
    lstm_rec_kernel<<<2 * NSL, 512, rec_smem>>>(w_hh_f, w_hh_b, c0);
    proj_kernel<<<TT, 576>>>(w_out, b_out);
    viterbi_kernel<<<BB, 32>>>(start_t, end_t, trans, out);
    crf_kernel<<<BB, 32>>>(tags, start_t, end_t, trans);
    finalize_kernel<<<1, 1>>>(out);
}